// round 2
// baseline (speedup 1.0000x reference)
#include <cuda_runtime.h>
#include <math.h>

#define BSZ 32
#define SEQ 1024
#define EMB 768
#define HD  64

// scratch for q,k,v (post-projection, post-RoPE) — static device arrays (no alloc)
__device__ float g_q[BSZ * SEQ * HD];
__device__ float g_k[BSZ * SEQ * HD];
__device__ float g_v[BSZ * SEQ * HD];

// ---------------------------------------------------------------------------
// Kernel 1: fused QKV projection + RoPE epilogue
//   grid = (M/64, 3)  [y: 0=q, 1=k, 2=v],  block = 256
// ---------------------------------------------------------------------------
__global__ __launch_bounds__(256) void qkv_rope_kernel(
    const float* __restrict__ x,
    const float* __restrict__ Wq,
    const float* __restrict__ Wk,
    const float* __restrict__ Wv)
{
    const int which = blockIdx.y;
    const float* __restrict__ W = (which == 0) ? Wq : ((which == 1) ? Wk : Wv);
    float* __restrict__ outp    = (which == 0) ? g_q : ((which == 1) ? g_k : g_v);

    const int m0 = blockIdx.x * 64;

    __shared__ float xs[32][65];   // [e-chunk][row]  (transposed)
    __shared__ float ws[32][65];   // [e-chunk][h]    (transposed)

    const int tid  = threadIdx.x;
    const int tx   = tid & 15;     // 0..15 -> cols (head dim) * 4
    const int ty   = tid >> 4;     // 0..15 -> rows * 4
    const int lcol = tid & 31;     // e offset within chunk
    const int lrow = tid >> 5;     // 0..7

    float acc[4][4] = {};

    for (int e0 = 0; e0 < EMB; e0 += 32) {
        #pragma unroll
        for (int p = 0; p < 8; p++) {
            const int r = lrow + p * 8;                       // 0..63
            xs[lcol][r] = x[(size_t)(m0 + r) * EMB + e0 + lcol];
            ws[lcol][r] = W[(size_t)r * EMB + e0 + lcol];     // h = r
        }
        __syncthreads();

        #pragma unroll
        for (int kk = 0; kk < 32; kk++) {
            float a0 = xs[kk][ty * 4 + 0];
            float a1 = xs[kk][ty * 4 + 1];
            float a2 = xs[kk][ty * 4 + 2];
            float a3 = xs[kk][ty * 4 + 3];
            float b0 = ws[kk][tx * 4 + 0];
            float b1 = ws[kk][tx * 4 + 1];
            float b2 = ws[kk][tx * 4 + 2];
            float b3 = ws[kk][tx * 4 + 3];
            acc[0][0] += a0 * b0; acc[0][1] += a0 * b1; acc[0][2] += a0 * b2; acc[0][3] += a0 * b3;
            acc[1][0] += a1 * b0; acc[1][1] += a1 * b1; acc[1][2] += a1 * b2; acc[1][3] += a1 * b3;
            acc[2][0] += a2 * b0; acc[2][1] += a2 * b1; acc[2][2] += a2 * b2; acc[2][3] += a2 * b3;
            acc[3][0] += a3 * b0; acc[3][1] += a3 * b1; acc[3][2] += a3 * b2; acc[3][3] += a3 * b3;
        }
        __syncthreads();
    }

    const int cbase = tx * 4;
    if (which < 2) {
        // RoPE (reference convention): theta_d = 10000^(-2d/64), d = even index
        // out[2i]   = a*cos - b*sin ; out[2i+1] = b*cos + a*sin
        #pragma unroll
        for (int i = 0; i < 4; i++) {
            const int row = m0 + ty * 4 + i;
            const float pos = (float)(row & (SEQ - 1));
            #pragma unroll
            for (int jp = 0; jp < 2; jp++) {
                const int d = cbase + jp * 2;                 // even dim index
                // -2*ln(10000)/64 = -0.28782313662428233
                const float theta = expf((float)d * -0.28782313662428233f);
                float sn, cs;
                sincosf(pos * theta, &sn, &cs);
                const float a = acc[i][jp * 2 + 0];
                const float b = acc[i][jp * 2 + 1];
                outp[(size_t)row * HD + d]     = a * cs - b * sn;
                outp[(size_t)row * HD + d + 1] = b * cs + a * sn;
            }
        }
    } else {
        #pragma unroll
        for (int i = 0; i < 4; i++) {
            const int row = m0 + ty * 4 + i;
            #pragma unroll
            for (int j = 0; j < 4; j++)
                outp[(size_t)row * HD + cbase + j] = acc[i][j];
        }
    }
}

// ---------------------------------------------------------------------------
// Kernel 2: causal flash attention (fp32, online softmax)
//   grid = (SEQ/64, BSZ), block = 256, dynamic smem = 4 * 64*65*4 bytes
// ---------------------------------------------------------------------------
#define TPAD 65

__global__ __launch_bounds__(256) void attn_kernel(float* __restrict__ out)
{
    extern __shared__ float sm[];
    float* Qs = sm;                     // 64 x 65
    float* Ks = Qs + 64 * TPAD;         // 64 x 65
    float* Vs = Ks + 64 * TPAD;         // 64 x 65
    float* Ps = Vs + 64 * TPAD;         // 64 x 65

    const int b  = blockIdx.y;
    const int q0 = blockIdx.x * 64;

    const float* __restrict__ qp = g_q + ((size_t)b * SEQ + q0) * HD;
    const float* __restrict__ kp = g_k + (size_t)b * SEQ * HD;
    const float* __restrict__ vp = g_v + (size_t)b * SEQ * HD;

    const int tid = threadIdx.x;
    const int tx  = tid & 15;
    const int ty  = tid >> 4;

    // load Q tile (contiguous 4096 floats) with pad insertion
    for (int p = tid; p < 64 * 16; p += 256) {
        float4 t = ((const float4*)qp)[p];
        const int r = p >> 4, h = (p & 15) * 4;
        float* d = &Qs[r * TPAD + h];
        d[0] = t.x; d[1] = t.y; d[2] = t.z; d[3] = t.w;
    }

    float m_r[4], l_r[4], o[4][4];
    #pragma unroll
    for (int i = 0; i < 4; i++) {
        m_r[i] = -1e30f; l_r[i] = 0.f;
        #pragma unroll
        for (int j = 0; j < 4; j++) o[i][j] = 0.f;
    }

    const float scale = 0.03608439182435161f;   // 768^-0.5
    const int ntiles = q0 / 64 + 1;

    for (int t = 0; t < ntiles; t++) {
        const int k0 = t * 64;
        __syncthreads();   // protect Ks/Vs/Ps reuse; also orders Q load on t==0

        for (int p = tid; p < 64 * 16; p += 256) {
            float4 tk = ((const float4*)(kp + (size_t)k0 * HD))[p];
            float4 tv = ((const float4*)(vp + (size_t)k0 * HD))[p];
            const int r = p >> 4, h = (p & 15) * 4;
            float* dk = &Ks[r * TPAD + h];
            dk[0] = tk.x; dk[1] = tk.y; dk[2] = tk.z; dk[3] = tk.w;
            float* dv = &Vs[r * TPAD + h];
            dv[0] = tv.x; dv[1] = tv.y; dv[2] = tv.z; dv[3] = tv.w;
        }
        __syncthreads();

        // S = Q K^T (4x4 per thread)
        float s[4][4] = {};
        #pragma unroll
        for (int h = 0; h < 64; h++) {
            float a0 = Qs[(ty * 4 + 0) * TPAD + h];
            float a1 = Qs[(ty * 4 + 1) * TPAD + h];
            float a2 = Qs[(ty * 4 + 2) * TPAD + h];
            float a3 = Qs[(ty * 4 + 3) * TPAD + h];
            float b0 = Ks[(tx * 4 + 0) * TPAD + h];
            float b1 = Ks[(tx * 4 + 1) * TPAD + h];
            float b2 = Ks[(tx * 4 + 2) * TPAD + h];
            float b3 = Ks[(tx * 4 + 3) * TPAD + h];
            s[0][0] += a0 * b0; s[0][1] += a0 * b1; s[0][2] += a0 * b2; s[0][3] += a0 * b3;
            s[1][0] += a1 * b0; s[1][1] += a1 * b1; s[1][2] += a1 * b2; s[1][3] += a1 * b3;
            s[2][0] += a2 * b0; s[2][1] += a2 * b1; s[2][2] += a2 * b2; s[2][3] += a2 * b3;
            s[3][0] += a3 * b0; s[3][1] += a3 * b1; s[3][2] += a3 * b2; s[3][3] += a3 * b3;
        }

        const bool diag = (k0 == q0);   // only diagonal tile needs masking
        #pragma unroll
        for (int i = 0; i < 4; i++) {
            #pragma unroll
            for (int j = 0; j < 4; j++) {
                float sv = s[i][j] * scale;
                if (diag && (tx * 4 + j > ty * 4 + i)) sv = -1e30f;
                s[i][j] = sv;
            }
        }

        // online softmax
        #pragma unroll
        for (int i = 0; i < 4; i++) {
            float rm = fmaxf(fmaxf(s[i][0], s[i][1]), fmaxf(s[i][2], s[i][3]));
            #pragma unroll
            for (int off = 8; off > 0; off >>= 1)
                rm = fmaxf(rm, __shfl_xor_sync(0xffffffffu, rm, off, 16));
            const float mnew  = fmaxf(m_r[i], rm);
            const float alpha = __expf(m_r[i] - mnew);
            m_r[i] = mnew;

            float rs = 0.f;
            #pragma unroll
            for (int j = 0; j < 4; j++) {
                const float p = __expf(s[i][j] - mnew);
                s[i][j] = p;
                rs += p;
            }
            #pragma unroll
            for (int off = 8; off > 0; off >>= 1)
                rs += __shfl_xor_sync(0xffffffffu, rs, off, 16);
            l_r[i] = l_r[i] * alpha + rs;
            #pragma unroll
            for (int j = 0; j < 4; j++) o[i][j] *= alpha;
        }

        // stage P
        #pragma unroll
        for (int i = 0; i < 4; i++)
            #pragma unroll
            for (int j = 0; j < 4; j++)
                Ps[(ty * 4 + i) * TPAD + tx * 4 + j] = s[i][j];
        __syncthreads();

        // O += P V
        #pragma unroll
        for (int kv = 0; kv < 64; kv++) {
            float p0 = Ps[(ty * 4 + 0) * TPAD + kv];
            float p1 = Ps[(ty * 4 + 1) * TPAD + kv];
            float p2 = Ps[(ty * 4 + 2) * TPAD + kv];
            float p3 = Ps[(ty * 4 + 3) * TPAD + kv];
            float v0 = Vs[kv * TPAD + tx * 4 + 0];
            float v1 = Vs[kv * TPAD + tx * 4 + 1];
            float v2 = Vs[kv * TPAD + tx * 4 + 2];
            float v3 = Vs[kv * TPAD + tx * 4 + 3];
            o[0][0] += p0 * v0; o[0][1] += p0 * v1; o[0][2] += p0 * v2; o[0][3] += p0 * v3;
            o[1][0] += p1 * v0; o[1][1] += p1 * v1; o[1][2] += p1 * v2; o[1][3] += p1 * v3;
            o[2][0] += p2 * v0; o[2][1] += p2 * v1; o[2][2] += p2 * v2; o[2][3] += p2 * v3;
            o[3][0] += p3 * v0; o[3][1] += p3 * v1; o[3][2] += p3 * v2; o[3][3] += p3 * v3;
        }
    }

    #pragma unroll
    for (int i = 0; i < 4; i++) {
        const float inv_l = 1.0f / l_r[i];
        #pragma unroll
        for (int j = 0; j < 4; j++)
            out[((size_t)b * SEQ + q0 + ty * 4 + i) * HD + tx * 4 + j] = o[i][j] * inv_l;
    }
}

extern "C" void kernel_launch(void* const* d_in, const int* in_sizes, int n_in,
                              void* d_out, int out_size)
{
    const float* x  = (const float*)d_in[0];
    const float* Wq = (const float*)d_in[1];
    const float* Wk = (const float*)d_in[2];
    const float* Wv = (const float*)d_in[3];
    float* out = (float*)d_out;

    // 1) QKV projection + RoPE -> g_q/g_k/g_v
    dim3 g1((BSZ * SEQ) / 64, 3);
    qkv_rope_kernel<<<g1, 256>>>(x, Wq, Wk, Wv);

    // 2) causal flash attention
    const int smem = 4 * 64 * TPAD * (int)sizeof(float);   // 66560 B
    cudaFuncSetAttribute(attn_kernel, cudaFuncAttributeMaxDynamicSharedMemorySize, smem);
    dim3 g2(SEQ / 64, BSZ);
    attn_kernel<<<g2, 256, smem>>>(out);
}

// round 3
// speedup vs baseline: 1.0417x; 1.0417x over previous
#include <cuda_runtime.h>
#include <math.h>

#define BSZ 32
#define SEQ 1024
#define EMB 768
#define HD  64

// scratch (static device arrays — no allocation)
__device__ float g_q[BSZ * SEQ * HD];
__device__ float g_k[BSZ * SEQ * HD];
__device__ float g_v[BSZ * SEQ * HD];
__device__ float g_cos[SEQ * 32];
__device__ float g_sin[SEQ * 32];

// ---------------------------------------------------------------------------
// Kernel 0: RoPE cos/sin table.  theta_pair = 10000^(-2*(2p)/64) = exp(-p*ln(1e4)/16)
// ---------------------------------------------------------------------------
__global__ void rope_table_kernel()
{
    const int t = blockIdx.x * blockDim.x + threadIdx.x;
    if (t >= SEQ * 32) return;
    const int pos = t >> 5;
    const int pr  = t & 31;
    const float theta = expf((float)pr * -0.5756462732485114f);
    float sn, cs;
    sincosf((float)pos * theta, &sn, &cs);
    g_cos[t] = cs;
    g_sin[t] = sn;
}

// ---------------------------------------------------------------------------
// Kernel 1: fused QKV projection + RoPE epilogue
//   grid = (32768/128, 3), block = 256.  Tile: 128 rows x 64 cols, micro 8x4.
// ---------------------------------------------------------------------------
__global__ __launch_bounds__(256) void qkv_rope_kernel(
    const float* __restrict__ x,
    const float* __restrict__ Wq,
    const float* __restrict__ Wk,
    const float* __restrict__ Wv)
{
    const int which = blockIdx.y;
    const float* __restrict__ W = (which == 0) ? Wq : ((which == 1) ? Wk : Wv);
    float* __restrict__ outp    = (which == 0) ? g_q : ((which == 1) ? g_k : g_v);

    const int m0 = blockIdx.x * 128;

    __shared__ float xs[32][129];   // [e-chunk][row], transposed (conflict-free: 129%32==1)
    __shared__ float ws[32][65];    // [e-chunk][h]

    const int tid  = threadIdx.x;
    const int tx   = tid & 15;      // 16 col-groups * 4
    const int ty   = tid >> 4;      // 16 row-groups * 8
    const int lcol = tid & 31;      // e within chunk
    const int lrow = tid >> 5;      // 0..7

    float acc[8][4] = {};

    for (int e0 = 0; e0 < EMB; e0 += 32) {
        #pragma unroll
        for (int p = 0; p < 16; p++) {
            const int r = lrow + p * 8;                        // 0..127
            xs[lcol][r] = x[(size_t)(m0 + r) * EMB + e0 + lcol];
        }
        #pragma unroll
        for (int p = 0; p < 8; p++) {
            const int h = lrow + p * 8;                        // 0..63
            ws[lcol][h] = W[(size_t)h * EMB + e0 + lcol];
        }
        __syncthreads();

        #pragma unroll
        for (int kk = 0; kk < 32; kk++) {
            float a[8], b[4];
            #pragma unroll
            for (int i = 0; i < 8; i++) a[i] = xs[kk][ty * 8 + i];
            #pragma unroll
            for (int j = 0; j < 4; j++) b[j] = ws[kk][tx * 4 + j];
            #pragma unroll
            for (int i = 0; i < 8; i++)
                #pragma unroll
                for (int j = 0; j < 4; j++)
                    acc[i][j] += a[i] * b[j];
        }
        __syncthreads();
    }

    const int cbase = tx * 4;
    if (which < 2) {
        #pragma unroll
        for (int i = 0; i < 8; i++) {
            const int row = m0 + ty * 8 + i;
            const int pos = row & (SEQ - 1);
            #pragma unroll
            for (int jp = 0; jp < 2; jp++) {
                const int d    = cbase + jp * 2;        // even dim index
                const int pair = tx * 2 + jp;           // d/2
                const float cs = g_cos[pos * 32 + pair];
                const float sn = g_sin[pos * 32 + pair];
                const float a = acc[i][jp * 2 + 0];
                const float b = acc[i][jp * 2 + 1];
                outp[(size_t)row * HD + d]     = a * cs - b * sn;
                outp[(size_t)row * HD + d + 1] = b * cs + a * sn;
            }
        }
    } else {
        #pragma unroll
        for (int i = 0; i < 8; i++) {
            const int row = m0 + ty * 8 + i;
            #pragma unroll
            for (int j = 0; j < 4; j++)
                outp[(size_t)row * HD + cbase + j] = acc[i][j];
        }
    }
}

// ---------------------------------------------------------------------------
// Kernel 2: causal flash attention, 128 threads, 64x64 tiles, micro 8x4.
//   grid = (16, 32); q-tile = 15 - blockIdx.x (largest work first).
// ---------------------------------------------------------------------------
#define TPAD 65

__global__ __launch_bounds__(128) void attn_kernel(float* __restrict__ out)
{
    extern __shared__ float sm[];
    float* Qs = sm;                     // 64 x 65
    float* Ks = Qs + 64 * TPAD;
    float* Vs = Ks + 64 * TPAD;
    float* Ps = Vs + 64 * TPAD;

    const int b  = blockIdx.y;
    const int qt = (SEQ / 64 - 1) - blockIdx.x;   // big blocks first
    const int q0 = qt * 64;

    const float* __restrict__ qp = g_q + ((size_t)b * SEQ + q0) * HD;
    const float* __restrict__ kp = g_k + (size_t)b * SEQ * HD;
    const float* __restrict__ vp = g_v + (size_t)b * SEQ * HD;

    const int tid = threadIdx.x;
    const int tx  = tid & 15;    // 16 col-groups * 4 (k dim / head dim)
    const int ty  = tid >> 4;    // 8 row-groups * 8 (q dim)

    // load Q tile
    for (int p = tid; p < 64 * 16; p += 128) {
        float4 t = ((const float4*)qp)[p];
        const int r = p >> 4, h = (p & 15) * 4;
        float* d = &Qs[r * TPAD + h];
        d[0] = t.x; d[1] = t.y; d[2] = t.z; d[3] = t.w;
    }

    float m_r[8], l_r[8], o[8][4];
    #pragma unroll
    for (int i = 0; i < 8; i++) {
        m_r[i] = -1e30f; l_r[i] = 0.f;
        #pragma unroll
        for (int j = 0; j < 4; j++) o[i][j] = 0.f;
    }

    const float scale = 0.03608439182435161f;   // 768^-0.5
    const int ntiles = qt + 1;

    for (int t = 0; t < ntiles; t++) {
        const int k0 = t * 64;
        __syncthreads();

        for (int p = tid; p < 64 * 16; p += 128) {
            float4 tk = ((const float4*)(kp + (size_t)k0 * HD))[p];
            float4 tv = ((const float4*)(vp + (size_t)k0 * HD))[p];
            const int r = p >> 4, h = (p & 15) * 4;
            float* dk = &Ks[r * TPAD + h];
            dk[0] = tk.x; dk[1] = tk.y; dk[2] = tk.z; dk[3] = tk.w;
            float* dv = &Vs[r * TPAD + h];
            dv[0] = tv.x; dv[1] = tv.y; dv[2] = tv.z; dv[3] = tv.w;
        }
        __syncthreads();

        // S = Q K^T : per-thread 8x4
        float s[8][4] = {};
        #pragma unroll
        for (int h = 0; h < 64; h++) {
            float a[8], bb[4];
            #pragma unroll
            for (int i = 0; i < 8; i++) a[i] = Qs[(ty * 8 + i) * TPAD + h];
            #pragma unroll
            for (int j = 0; j < 4; j++) bb[j] = Ks[(tx * 4 + j) * TPAD + h];
            #pragma unroll
            for (int i = 0; i < 8; i++)
                #pragma unroll
                for (int j = 0; j < 4; j++)
                    s[i][j] += a[i] * bb[j];
        }

        const bool diag = (k0 == q0);
        #pragma unroll
        for (int i = 0; i < 8; i++) {
            #pragma unroll
            for (int j = 0; j < 4; j++) {
                float sv = s[i][j] * scale;
                if (diag && (tx * 4 + j > ty * 8 + i)) sv = -1e30f;
                s[i][j] = sv;
            }
        }

        // online softmax (row reduction over 16 lanes in x)
        #pragma unroll
        for (int i = 0; i < 8; i++) {
            float rm = fmaxf(fmaxf(s[i][0], s[i][1]), fmaxf(s[i][2], s[i][3]));
            #pragma unroll
            for (int off = 8; off > 0; off >>= 1)
                rm = fmaxf(rm, __shfl_xor_sync(0xffffffffu, rm, off, 16));
            const float mnew  = fmaxf(m_r[i], rm);
            const float alpha = __expf(m_r[i] - mnew);
            m_r[i] = mnew;

            float rs = 0.f;
            #pragma unroll
            for (int j = 0; j < 4; j++) {
                const float p = __expf(s[i][j] - mnew);
                s[i][j] = p;
                rs += p;
            }
            #pragma unroll
            for (int off = 8; off > 0; off >>= 1)
                rs += __shfl_xor_sync(0xffffffffu, rs, off, 16);
            l_r[i] = l_r[i] * alpha + rs;
            #pragma unroll
            for (int j = 0; j < 4; j++) o[i][j] *= alpha;
        }

        // stage P
        #pragma unroll
        for (int i = 0; i < 8; i++)
            #pragma unroll
            for (int j = 0; j < 4; j++)
                Ps[(ty * 8 + i) * TPAD + tx * 4 + j] = s[i][j];
        __syncthreads();

        // O += P V
        #pragma unroll
        for (int kv = 0; kv < 64; kv++) {
            float p[8], vv[4];
            #pragma unroll
            for (int i = 0; i < 8; i++) p[i] = Ps[(ty * 8 + i) * TPAD + kv];
            #pragma unroll
            for (int j = 0; j < 4; j++) vv[j] = Vs[kv * TPAD + tx * 4 + j];
            #pragma unroll
            for (int i = 0; i < 8; i++)
                #pragma unroll
                for (int j = 0; j < 4; j++)
                    o[i][j] += p[i] * vv[j];
        }
    }

    #pragma unroll
    for (int i = 0; i < 8; i++) {
        const float inv_l = 1.0f / l_r[i];
        #pragma unroll
        for (int j = 0; j < 4; j++)
            out[((size_t)b * SEQ + q0 + ty * 8 + i) * HD + tx * 4 + j] = o[i][j] * inv_l;
    }
}

extern "C" void kernel_launch(void* const* d_in, const int* in_sizes, int n_in,
                              void* d_out, int out_size)
{
    const float* x  = (const float*)d_in[0];
    const float* Wq = (const float*)d_in[1];
    const float* Wk = (const float*)d_in[2];
    const float* Wv = (const float*)d_in[3];
    float* out = (float*)d_out;

    // 0) RoPE tables
    rope_table_kernel<<<(SEQ * 32 + 255) / 256, 256>>>();

    // 1) QKV projection + RoPE -> g_q/g_k/g_v
    dim3 g1((BSZ * SEQ) / 128, 3);
    qkv_rope_kernel<<<g1, 256>>>(x, Wq, Wk, Wv);

    // 2) causal flash attention (largest q-tiles first)
    const int smem = 4 * 64 * TPAD * (int)sizeof(float);   // 66560 B
    cudaFuncSetAttribute(attn_kernel, cudaFuncAttributeMaxDynamicSharedMemorySize, smem);
    dim3 g2(SEQ / 64, BSZ);
    attn_kernel<<<g2, 128, smem>>>(out);
}

// round 4
// speedup vs baseline: 1.4111x; 1.3546x over previous
#include <cuda_runtime.h>
#include <math.h>

#define BSZ 32
#define SEQ 1024
#define EMB 768
#define HD  64

typedef unsigned long long ull;

// packed f32x2 helpers (Blackwell FFMA2 path — PTX-only)
__device__ __forceinline__ ull pk2(float lo, float hi) {
    ull r; asm("mov.b64 %0, {%1, %2};" : "=l"(r) : "f"(lo), "f"(hi)); return r;
}
__device__ __forceinline__ void upk2(ull v, float& lo, float& hi) {
    asm("mov.b64 {%0, %1}, %2;" : "=f"(lo), "=f"(hi) : "l"(v));
}
__device__ __forceinline__ ull fma2(ull a, ull b, ull c) {
    ull d; asm("fma.rn.f32x2 %0, %1, %2, %3;" : "=l"(d) : "l"(a), "l"(b), "l"(c)); return d;
}
__device__ __forceinline__ ull mul2(ull a, ull b) {
    ull d; asm("mul.rn.f32x2 %0, %1, %2;" : "=l"(d) : "l"(a), "l"(b)); return d;
}

// scratch (static device arrays — no allocation)
__device__ float g_q[BSZ * SEQ * HD];
__device__ float g_k[BSZ * SEQ * HD];
__device__ float g_v[BSZ * SEQ * HD];
__device__ float g_cos[SEQ * 32];
__device__ float g_sin[SEQ * 32];

// ---------------------------------------------------------------------------
// Kernel 0: RoPE cos/sin table. theta_pair = exp(-p * ln(1e4)/16)
// ---------------------------------------------------------------------------
__global__ void rope_table_kernel()
{
    const int t = blockIdx.x * blockDim.x + threadIdx.x;
    if (t >= SEQ * 32) return;
    const int pos = t >> 5;
    const int pr  = t & 31;
    const float theta = expf((float)pr * -0.5756462732485114f);
    float sn, cs;
    sincosf((float)pos * theta, &sn, &cs);
    g_cos[t] = cs;
    g_sin[t] = sn;
}

// ---------------------------------------------------------------------------
// Kernel 1: fused QKV projection + RoPE epilogue (FFMA2 inner loop)
//   grid = (32768/128, 3), block = 256. Tile 128x64, micro 8x4 (rows packed).
// ---------------------------------------------------------------------------
__global__ __launch_bounds__(256) void qkv_rope_kernel(
    const float* __restrict__ x,
    const float* __restrict__ Wq,
    const float* __restrict__ Wk,
    const float* __restrict__ Wv)
{
    const int which = blockIdx.y;
    const float* __restrict__ W = (which == 0) ? Wq : ((which == 1) ? Wk : Wv);
    float* __restrict__ outp    = (which == 0) ? g_q : ((which == 1) ? g_k : g_v);

    const int m0 = blockIdx.x * 128;

    __shared__ float xs[32][130];   // [e][row] — rows contiguous, even pad for LDS.64
    __shared__ float ws[32][65];    // [e][h]

    const int tid  = threadIdx.x;
    const int tx   = tid & 15;
    const int ty   = tid >> 4;
    const int lcol = tid & 31;
    const int lrow = tid >> 5;

    ull acc2[4][4];
    #pragma unroll
    for (int i = 0; i < 4; i++)
        #pragma unroll
        for (int j = 0; j < 4; j++) acc2[i][j] = 0ull;

    for (int e0 = 0; e0 < EMB; e0 += 32) {
        #pragma unroll
        for (int p = 0; p < 16; p++) {
            const int r = lrow + p * 8;
            xs[lcol][r] = x[(size_t)(m0 + r) * EMB + e0 + lcol];
        }
        #pragma unroll
        for (int p = 0; p < 8; p++) {
            const int h = lrow + p * 8;
            ws[lcol][h] = W[(size_t)h * EMB + e0 + lcol];
        }
        __syncthreads();

        #pragma unroll
        for (int kk = 0; kk < 32; kk++) {
            const ull* ap = (const ull*)&xs[kk][ty * 8];
            ull a2[4];
            #pragma unroll
            for (int i2 = 0; i2 < 4; i2++) a2[i2] = ap[i2];
            ull b2[4];
            #pragma unroll
            for (int j = 0; j < 4; j++) {
                const float bv = ws[kk][tx * 4 + j];
                b2[j] = pk2(bv, bv);
            }
            #pragma unroll
            for (int i2 = 0; i2 < 4; i2++)
                #pragma unroll
                for (int j = 0; j < 4; j++)
                    acc2[i2][j] = fma2(a2[i2], b2[j], acc2[i2][j]);
        }
        __syncthreads();
    }

    if (which < 2) {
        #pragma unroll
        for (int i2 = 0; i2 < 4; i2++) {
            const int r0 = m0 + ty * 8 + 2 * i2;
            const int p0 = r0 & (SEQ - 1);
            const int p1 = (r0 + 1) & (SEQ - 1);
            #pragma unroll
            for (int jp = 0; jp < 2; jp++) {
                const int pair = tx * 2 + jp;
                const int d    = tx * 4 + 2 * jp;
                const ull cs2 = pk2(g_cos[p0 * 32 + pair], g_cos[p1 * 32 + pair]);
                const ull sn2 = pk2(g_sin[p0 * 32 + pair], g_sin[p1 * 32 + pair]);
                float s0, s1; upk2(sn2, s0, s1);
                const ull nsn2 = pk2(-s0, -s1);
                const ull a = acc2[i2][2 * jp + 0];
                const ull b = acc2[i2][2 * jp + 1];
                const ull o0 = fma2(b, nsn2, mul2(a, cs2));  // dim d
                const ull o1 = fma2(b, cs2,  mul2(a, sn2));  // dim d+1
                float o0l, o0h, o1l, o1h;
                upk2(o0, o0l, o0h); upk2(o1, o1l, o1h);
                *(ull*)&outp[(size_t)r0 * HD + d]       = pk2(o0l, o1l);
                *(ull*)&outp[(size_t)(r0 + 1) * HD + d] = pk2(o0h, o1h);
            }
        }
    } else {
        #pragma unroll
        for (int i2 = 0; i2 < 4; i2++) {
            const int r0 = m0 + ty * 8 + 2 * i2;
            float v0[4], v1[4];
            #pragma unroll
            for (int j = 0; j < 4; j++) upk2(acc2[i2][j], v0[j], v1[j]);
            *(float4*)&outp[(size_t)r0 * HD + tx * 4]       = make_float4(v0[0], v0[1], v0[2], v0[3]);
            *(float4*)&outp[(size_t)(r0 + 1) * HD + tx * 4] = make_float4(v1[0], v1[1], v1[2], v1[3]);
        }
    }
}

// ---------------------------------------------------------------------------
// Kernel 2: causal flash attention, FFMA2 inner loops.
//   128 threads, 64x64 tiles, micro 8x4 (q-rows packed).
//   Qs/Ps stored transposed (row-contiguous) for LDS.64 pair loads.
// ---------------------------------------------------------------------------
#define QP 66   // Qs_t / Ps_t row-dim pad (even, conflict-light)
#define KP 65   // Ks / Vs head-dim pad

__global__ __launch_bounds__(128) void attn_kernel(float* __restrict__ out)
{
    extern __shared__ float sm[];
    float* Qt = sm;                  // [h][qr]   64 x 66
    float* Ks = Qt + 64 * QP;        // [kr][h]   64 x 65
    float* Vs = Ks + 64 * KP;        // [kr][h]   64 x 65
    float* Pt = Vs + 64 * KP;        // [kv][qr]  64 x 66

    const int b  = blockIdx.y;
    const int qt = (SEQ / 64 - 1) - blockIdx.x;   // largest work first
    const int q0 = qt * 64;

    const float* __restrict__ qp = g_q + ((size_t)b * SEQ + q0) * HD;
    const float* __restrict__ kp = g_k + (size_t)b * SEQ * HD;
    const float* __restrict__ vp = g_v + (size_t)b * SEQ * HD;

    const int tid = threadIdx.x;
    const int tx  = tid & 15;
    const int ty  = tid >> 4;

    // load Q tile transposed: Qt[h][qr]
    for (int p = tid; p < 64 * 16; p += 128) {
        float4 t = ((const float4*)qp)[p];
        const int r = p >> 4, h = (p & 15) * 4;
        Qt[(h + 0) * QP + r] = t.x;
        Qt[(h + 1) * QP + r] = t.y;
        Qt[(h + 2) * QP + r] = t.z;
        Qt[(h + 3) * QP + r] = t.w;
    }

    float m_r[8], l_r[8];
    ull o2[4][4];
    #pragma unroll
    for (int i = 0; i < 8; i++) { m_r[i] = -1e30f; l_r[i] = 0.f; }
    #pragma unroll
    for (int i2 = 0; i2 < 4; i2++)
        #pragma unroll
        for (int j = 0; j < 4; j++) o2[i2][j] = 0ull;

    const float scale = 0.03608439182435161f;   // 768^-0.5
    const int ntiles = qt + 1;

    for (int t = 0; t < ntiles; t++) {
        const int k0 = t * 64;
        __syncthreads();

        for (int p = tid; p < 64 * 16; p += 128) {
            float4 tk = ((const float4*)(kp + (size_t)k0 * HD))[p];
            float4 tv = ((const float4*)(vp + (size_t)k0 * HD))[p];
            const int r = p >> 4, h = (p & 15) * 4;
            float* dk = &Ks[r * KP + h];
            dk[0] = tk.x; dk[1] = tk.y; dk[2] = tk.z; dk[3] = tk.w;
            float* dv = &Vs[r * KP + h];
            dv[0] = tv.x; dv[1] = tv.y; dv[2] = tv.z; dv[3] = tv.w;
        }
        __syncthreads();

        // S = Q K^T : packed pairs over q-rows
        ull s2[4][4];
        #pragma unroll
        for (int i2 = 0; i2 < 4; i2++)
            #pragma unroll
            for (int j = 0; j < 4; j++) s2[i2][j] = 0ull;

        #pragma unroll
        for (int h = 0; h < 64; h++) {
            const ull* ap = (const ull*)&Qt[h * QP + ty * 8];
            ull a2[4];
            #pragma unroll
            for (int i2 = 0; i2 < 4; i2++) a2[i2] = ap[i2];
            ull b2[4];
            #pragma unroll
            for (int j = 0; j < 4; j++) {
                const float bv = Ks[(tx * 4 + j) * KP + h];
                b2[j] = pk2(bv, bv);
            }
            #pragma unroll
            for (int i2 = 0; i2 < 4; i2++)
                #pragma unroll
                for (int j = 0; j < 4; j++)
                    s2[i2][j] = fma2(a2[i2], b2[j], s2[i2][j]);
        }

        // unpack, scale, mask
        float s[8][4];
        #pragma unroll
        for (int i2 = 0; i2 < 4; i2++)
            #pragma unroll
            for (int j = 0; j < 4; j++)
                upk2(s2[i2][j], s[2 * i2][j], s[2 * i2 + 1][j]);

        const bool diag = (k0 == q0);
        #pragma unroll
        for (int i = 0; i < 8; i++)
            #pragma unroll
            for (int j = 0; j < 4; j++) {
                float sv = s[i][j] * scale;
                if (diag && (tx * 4 + j > ty * 8 + i)) sv = -1e30f;
                s[i][j] = sv;
            }

        // online softmax (16-lane row reductions)
        float alpha[8];
        #pragma unroll
        for (int i = 0; i < 8; i++) {
            float rm = fmaxf(fmaxf(s[i][0], s[i][1]), fmaxf(s[i][2], s[i][3]));
            #pragma unroll
            for (int off = 8; off > 0; off >>= 1)
                rm = fmaxf(rm, __shfl_xor_sync(0xffffffffu, rm, off, 16));
            const float mnew = fmaxf(m_r[i], rm);
            alpha[i] = __expf(m_r[i] - mnew);
            m_r[i] = mnew;

            float rs = 0.f;
            #pragma unroll
            for (int j = 0; j < 4; j++) {
                const float p = __expf(s[i][j] - mnew);
                s[i][j] = p;
                rs += p;
            }
            #pragma unroll
            for (int off = 8; off > 0; off >>= 1)
                rs += __shfl_xor_sync(0xffffffffu, rs, off, 16);
            l_r[i] = l_r[i] * alpha[i] + rs;
        }

        // rescale o (packed) and stage P transposed (pairs over q-rows)
        #pragma unroll
        for (int i2 = 0; i2 < 4; i2++) {
            const ull al2 = pk2(alpha[2 * i2], alpha[2 * i2 + 1]);
            #pragma unroll
            for (int j = 0; j < 4; j++) {
                o2[i2][j] = mul2(o2[i2][j], al2);
                ((ull*)&Pt[(tx * 4 + j) * QP + ty * 8])[i2] = pk2(s[2 * i2][j], s[2 * i2 + 1][j]);
            }
        }
        __syncthreads();

        // O += P V : packed pairs over q-rows
        #pragma unroll
        for (int kv = 0; kv < 64; kv++) {
            const ull* pp = (const ull*)&Pt[kv * QP + ty * 8];
            ull p2[4];
            #pragma unroll
            for (int i2 = 0; i2 < 4; i2++) p2[i2] = pp[i2];
            ull v2[4];
            #pragma unroll
            for (int j = 0; j < 4; j++) {
                const float vv = Vs[kv * KP + tx * 4 + j];
                v2[j] = pk2(vv, vv);
            }
            #pragma unroll
            for (int i2 = 0; i2 < 4; i2++)
                #pragma unroll
                for (int j = 0; j < 4; j++)
                    o2[i2][j] = fma2(p2[i2], v2[j], o2[i2][j]);
        }
    }

    #pragma unroll
    for (int i2 = 0; i2 < 4; i2++) {
        const int r0 = q0 + ty * 8 + 2 * i2;
        const float il0 = 1.0f / l_r[2 * i2];
        const float il1 = 1.0f / l_r[2 * i2 + 1];
        float v0[4], v1[4];
        #pragma unroll
        for (int j = 0; j < 4; j++) {
            upk2(o2[i2][j], v0[j], v1[j]);
            v0[j] *= il0; v1[j] *= il1;
        }
        *(float4*)&out[((size_t)b * SEQ + r0) * HD + tx * 4]     = make_float4(v0[0], v0[1], v0[2], v0[3]);
        *(float4*)&out[((size_t)b * SEQ + r0 + 1) * HD + tx * 4] = make_float4(v1[0], v1[1], v1[2], v1[3]);
    }
}

extern "C" void kernel_launch(void* const* d_in, const int* in_sizes, int n_in,
                              void* d_out, int out_size)
{
    const float* x  = (const float*)d_in[0];
    const float* Wq = (const float*)d_in[1];
    const float* Wk = (const float*)d_in[2];
    const float* Wv = (const float*)d_in[3];
    float* out = (float*)d_out;

    rope_table_kernel<<<(SEQ * 32 + 255) / 256, 256>>>();

    dim3 g1((BSZ * SEQ) / 128, 3);
    qkv_rope_kernel<<<g1, 256>>>(x, Wq, Wk, Wv);

    const int smem = (2 * 64 * QP + 2 * 64 * KP) * (int)sizeof(float);   // 67072 B
    cudaFuncSetAttribute(attn_kernel, cudaFuncAttributeMaxDynamicSharedMemorySize, smem);
    dim3 g2(SEQ / 64, BSZ);
    attn_kernel<<<g2, 128, smem>>>(out);
}

// round 5
// speedup vs baseline: 2.0426x; 1.4475x over previous
#include <cuda_runtime.h>
#include <math.h>

#define BSZ 32
#define SEQ 1024
#define EMB 768
#define HD  64

typedef unsigned long long ull;
typedef unsigned int uint32;

// ---- packed f32x2 helpers (Blackwell FFMA2 path) ----
__device__ __forceinline__ ull pk2(float lo, float hi) {
    ull r; asm("mov.b64 %0, {%1, %2};" : "=l"(r) : "f"(lo), "f"(hi)); return r;
}
__device__ __forceinline__ void upk2(ull v, float& lo, float& hi) {
    asm("mov.b64 {%0, %1}, %2;" : "=f"(lo), "=f"(hi) : "l"(v));
}
__device__ __forceinline__ ull fma2(ull a, ull b, ull c) {
    ull d; asm("fma.rn.f32x2 %0, %1, %2, %3;" : "=l"(d) : "l"(a), "l"(b), "l"(c)); return d;
}
__device__ __forceinline__ ull mul2(ull a, ull b) {
    ull d; asm("mul.rn.f32x2 %0, %1, %2;" : "=l"(d) : "l"(a), "l"(b)); return d;
}

// ---- tf32 mma helpers ----
__device__ __forceinline__ uint32 f2tf32(float x) {
    uint32 y; asm("cvt.rna.tf32.f32 %0, %1;" : "=r"(y) : "f"(x)); return y;
}
__device__ __forceinline__ void mma_tf32(float c[4],
    uint32 a0, uint32 a1, uint32 a2, uint32 a3, uint32 b0, uint32 b1)
{
    asm volatile(
        "mma.sync.aligned.m16n8k8.row.col.f32.tf32.tf32.f32 "
        "{%0,%1,%2,%3}, {%4,%5,%6,%7}, {%8,%9}, {%0,%1,%2,%3};"
        : "+f"(c[0]), "+f"(c[1]), "+f"(c[2]), "+f"(c[3])
        : "r"(a0), "r"(a1), "r"(a2), "r"(a3), "r"(b0), "r"(b1));
}

// scratch (static device arrays — no allocation)
__device__ float g_q[BSZ * SEQ * HD];
__device__ float g_k[BSZ * SEQ * HD];
__device__ float g_v[BSZ * SEQ * HD];
__device__ float g_cos[SEQ * 32];
__device__ float g_sin[SEQ * 32];

// ---------------------------------------------------------------------------
// Kernel 0: RoPE cos/sin table. theta_pair = exp(-p * ln(1e4)/16)
// ---------------------------------------------------------------------------
__global__ void rope_table_kernel()
{
    const int t = blockIdx.x * blockDim.x + threadIdx.x;
    if (t >= SEQ * 32) return;
    const int pos = t >> 5;
    const int pr  = t & 31;
    const float theta = expf((float)pr * -0.5756462732485114f);
    float sn, cs;
    sincosf((float)pos * theta, &sn, &cs);
    g_cos[t] = cs;
    g_sin[t] = sn;
}

// ---------------------------------------------------------------------------
// Kernel 1: QKV projection via mma.sync tf32 + RoPE epilogue.
//   grid=(32768/128, 3), 256 thr (8 warps). Block tile 128x64, warp tile 32x32.
//   Smem stride 36 floats: bank(a-frag) = (4r + c) % 32 — conflict-free.
// ---------------------------------------------------------------------------
#define SSTR 36

__global__ __launch_bounds__(256) void qkv_rope_kernel(
    const float* __restrict__ x,
    const float* __restrict__ Wq,
    const float* __restrict__ Wk,
    const float* __restrict__ Wv)
{
    const int which = blockIdx.y;
    const float* __restrict__ W = (which == 0) ? Wq : ((which == 1) ? Wk : Wv);
    float* __restrict__ outp    = (which == 0) ? g_q : ((which == 1) ? g_k : g_v);

    const int m0 = blockIdx.x * 128;

    __shared__ uint32 xs[128 * SSTR];
    __shared__ uint32 ws[64 * SSTR];

    const int tid    = threadIdx.x;
    const int lane   = tid & 31;
    const int wid    = tid >> 5;
    const int warp_m = wid & 3;    // 4 warps over M (32 rows each)
    const int warp_n = wid >> 2;   // 2 warps over N (32 cols each)
    const int lr = lane >> 2;      // 0..7
    const int lc = lane & 3;       // 0..3

    float c[2][4][4];
    #pragma unroll
    for (int mt = 0; mt < 2; mt++)
        #pragma unroll
        for (int nt = 0; nt < 4; nt++)
            #pragma unroll
            for (int r = 0; r < 4; r++) c[mt][nt][r] = 0.f;

    for (int e0 = 0; e0 < EMB; e0 += 32) {
        __syncthreads();
        // stage x tile 128x32 (tf32)
        #pragma unroll
        for (int q = 0; q < 4; q++) {
            const int p = tid + q * 256;         // 0..1023 float4s
            const int row = p >> 3, kq = p & 7;
            float4 t = *(const float4*)&x[(size_t)(m0 + row) * EMB + e0 + kq * 4];
            uint32* d = &xs[row * SSTR + kq * 4];
            d[0] = f2tf32(t.x); d[1] = f2tf32(t.y); d[2] = f2tf32(t.z); d[3] = f2tf32(t.w);
        }
        // stage W tile 64x32 (tf32)
        #pragma unroll
        for (int q = 0; q < 2; q++) {
            const int p = tid + q * 256;         // 0..511
            const int row = p >> 3, kq = p & 7;
            float4 t = *(const float4*)&W[(size_t)row * EMB + e0 + kq * 4];
            uint32* d = &ws[row * SSTR + kq * 4];
            d[0] = f2tf32(t.x); d[1] = f2tf32(t.y); d[2] = f2tf32(t.z); d[3] = f2tf32(t.w);
        }
        __syncthreads();

        #pragma unroll
        for (int ks = 0; ks < 4; ks++) {
            const int k0 = ks * 8;
            uint32 a[2][4];
            #pragma unroll
            for (int mt = 0; mt < 2; mt++) {
                const int rb = warp_m * 32 + mt * 16 + lr;
                a[mt][0] = xs[rb * SSTR + k0 + lc];
                a[mt][1] = xs[(rb + 8) * SSTR + k0 + lc];
                a[mt][2] = xs[rb * SSTR + k0 + lc + 4];
                a[mt][3] = xs[(rb + 8) * SSTR + k0 + lc + 4];
            }
            uint32 bb[4][2];
            #pragma unroll
            for (int nt = 0; nt < 4; nt++) {
                const int nb = warp_n * 32 + nt * 8 + lr;
                bb[nt][0] = ws[nb * SSTR + k0 + lc];
                bb[nt][1] = ws[nb * SSTR + k0 + lc + 4];
            }
            #pragma unroll
            for (int mt = 0; mt < 2; mt++)
                #pragma unroll
                for (int nt = 0; nt < 4; nt++)
                    mma_tf32(c[mt][nt], a[mt][0], a[mt][1], a[mt][2], a[mt][3],
                             bb[nt][0], bb[nt][1]);
        }
    }

    // epilogue: C frag cols are (2*lc, 2*lc+1) — exactly a RoPE pair
    if (which < 2) {
        #pragma unroll
        for (int mt = 0; mt < 2; mt++) {
            const int r0 = m0 + warp_m * 32 + mt * 16 + lr;
            const int r1 = r0 + 8;
            const int p0 = r0 & (SEQ - 1);
            const int p1 = r1 & (SEQ - 1);
            #pragma unroll
            for (int nt = 0; nt < 4; nt++) {
                const int d0   = warp_n * 32 + nt * 8 + 2 * lc;
                const int pair = d0 >> 1;
                {
                    const float cs = g_cos[p0 * 32 + pair];
                    const float sn = g_sin[p0 * 32 + pair];
                    const float av = c[mt][nt][0], bv = c[mt][nt][1];
                    *(ull*)&outp[(size_t)r0 * HD + d0] = pk2(av * cs - bv * sn, bv * cs + av * sn);
                }
                {
                    const float cs = g_cos[p1 * 32 + pair];
                    const float sn = g_sin[p1 * 32 + pair];
                    const float av = c[mt][nt][2], bv = c[mt][nt][3];
                    *(ull*)&outp[(size_t)r1 * HD + d0] = pk2(av * cs - bv * sn, bv * cs + av * sn);
                }
            }
        }
    } else {
        #pragma unroll
        for (int mt = 0; mt < 2; mt++) {
            const int r0 = m0 + warp_m * 32 + mt * 16 + lr;
            #pragma unroll
            for (int nt = 0; nt < 4; nt++) {
                const int d0 = warp_n * 32 + nt * 8 + 2 * lc;
                *(ull*)&outp[(size_t)r0 * HD + d0]       = pk2(c[mt][nt][0], c[mt][nt][1]);
                *(ull*)&outp[(size_t)(r0 + 8) * HD + d0] = pk2(c[mt][nt][2], c[mt][nt][3]);
            }
        }
    }
}

// ---------------------------------------------------------------------------
// Kernel 2: causal flash attention, FFMA2 inner loops (unchanged from R4).
// ---------------------------------------------------------------------------
#define QP 66
#define KP 65

__global__ __launch_bounds__(128) void attn_kernel(float* __restrict__ out)
{
    extern __shared__ float sm[];
    float* Qt = sm;                  // [h][qr]   64 x 66
    float* Ks = Qt + 64 * QP;        // [kr][h]   64 x 65
    float* Vs = Ks + 64 * KP;        // [kr][h]   64 x 65
    float* Pt = Vs + 64 * KP;        // [kv][qr]  64 x 66

    const int b  = blockIdx.y;
    const int qt = (SEQ / 64 - 1) - blockIdx.x;   // largest work first
    const int q0 = qt * 64;

    const float* __restrict__ qp = g_q + ((size_t)b * SEQ + q0) * HD;
    const float* __restrict__ kp = g_k + (size_t)b * SEQ * HD;
    const float* __restrict__ vp = g_v + (size_t)b * SEQ * HD;

    const int tid = threadIdx.x;
    const int tx  = tid & 15;
    const int ty  = tid >> 4;

    for (int p = tid; p < 64 * 16; p += 128) {
        float4 t = ((const float4*)qp)[p];
        const int r = p >> 4, h = (p & 15) * 4;
        Qt[(h + 0) * QP + r] = t.x;
        Qt[(h + 1) * QP + r] = t.y;
        Qt[(h + 2) * QP + r] = t.z;
        Qt[(h + 3) * QP + r] = t.w;
    }

    float m_r[8], l_r[8];
    ull o2[4][4];
    #pragma unroll
    for (int i = 0; i < 8; i++) { m_r[i] = -1e30f; l_r[i] = 0.f; }
    #pragma unroll
    for (int i2 = 0; i2 < 4; i2++)
        #pragma unroll
        for (int j = 0; j < 4; j++) o2[i2][j] = 0ull;

    const float scale = 0.03608439182435161f;
    const int ntiles = qt + 1;

    for (int t = 0; t < ntiles; t++) {
        const int k0 = t * 64;
        __syncthreads();

        for (int p = tid; p < 64 * 16; p += 128) {
            float4 tk = ((const float4*)(kp + (size_t)k0 * HD))[p];
            float4 tv = ((const float4*)(vp + (size_t)k0 * HD))[p];
            const int r = p >> 4, h = (p & 15) * 4;
            float* dk = &Ks[r * KP + h];
            dk[0] = tk.x; dk[1] = tk.y; dk[2] = tk.z; dk[3] = tk.w;
            float* dv = &Vs[r * KP + h];
            dv[0] = tv.x; dv[1] = tv.y; dv[2] = tv.z; dv[3] = tv.w;
        }
        __syncthreads();

        ull s2[4][4];
        #pragma unroll
        for (int i2 = 0; i2 < 4; i2++)
            #pragma unroll
            for (int j = 0; j < 4; j++) s2[i2][j] = 0ull;

        #pragma unroll
        for (int h = 0; h < 64; h++) {
            const ull* ap = (const ull*)&Qt[h * QP + ty * 8];
            ull a2[4];
            #pragma unroll
            for (int i2 = 0; i2 < 4; i2++) a2[i2] = ap[i2];
            ull b2[4];
            #pragma unroll
            for (int j = 0; j < 4; j++) {
                const float bv = Ks[(tx * 4 + j) * KP + h];
                b2[j] = pk2(bv, bv);
            }
            #pragma unroll
            for (int i2 = 0; i2 < 4; i2++)
                #pragma unroll
                for (int j = 0; j < 4; j++)
                    s2[i2][j] = fma2(a2[i2], b2[j], s2[i2][j]);
        }

        float s[8][4];
        #pragma unroll
        for (int i2 = 0; i2 < 4; i2++)
            #pragma unroll
            for (int j = 0; j < 4; j++)
                upk2(s2[i2][j], s[2 * i2][j], s[2 * i2 + 1][j]);

        const bool diag = (k0 == q0);
        #pragma unroll
        for (int i = 0; i < 8; i++)
            #pragma unroll
            for (int j = 0; j < 4; j++) {
                float sv = s[i][j] * scale;
                if (diag && (tx * 4 + j > ty * 8 + i)) sv = -1e30f;
                s[i][j] = sv;
            }

        float alpha[8];
        #pragma unroll
        for (int i = 0; i < 8; i++) {
            float rm = fmaxf(fmaxf(s[i][0], s[i][1]), fmaxf(s[i][2], s[i][3]));
            #pragma unroll
            for (int off = 8; off > 0; off >>= 1)
                rm = fmaxf(rm, __shfl_xor_sync(0xffffffffu, rm, off, 16));
            const float mnew = fmaxf(m_r[i], rm);
            alpha[i] = __expf(m_r[i] - mnew);
            m_r[i] = mnew;

            float rs = 0.f;
            #pragma unroll
            for (int j = 0; j < 4; j++) {
                const float p = __expf(s[i][j] - mnew);
                s[i][j] = p;
                rs += p;
            }
            #pragma unroll
            for (int off = 8; off > 0; off >>= 1)
                rs += __shfl_xor_sync(0xffffffffu, rs, off, 16);
            l_r[i] = l_r[i] * alpha[i] + rs;
        }

        #pragma unroll
        for (int i2 = 0; i2 < 4; i2++) {
            const ull al2 = pk2(alpha[2 * i2], alpha[2 * i2 + 1]);
            #pragma unroll
            for (int j = 0; j < 4; j++) {
                o2[i2][j] = mul2(o2[i2][j], al2);
                ((ull*)&Pt[(tx * 4 + j) * QP + ty * 8])[i2] = pk2(s[2 * i2][j], s[2 * i2 + 1][j]);
            }
        }
        __syncthreads();

        #pragma unroll
        for (int kv = 0; kv < 64; kv++) {
            const ull* pp = (const ull*)&Pt[kv * QP + ty * 8];
            ull p2[4];
            #pragma unroll
            for (int i2 = 0; i2 < 4; i2++) p2[i2] = pp[i2];
            ull v2[4];
            #pragma unroll
            for (int j = 0; j < 4; j++) {
                const float vv = Vs[kv * KP + tx * 4 + j];
                v2[j] = pk2(vv, vv);
            }
            #pragma unroll
            for (int i2 = 0; i2 < 4; i2++)
                #pragma unroll
                for (int j = 0; j < 4; j++)
                    o2[i2][j] = fma2(p2[i2], v2[j], o2[i2][j]);
        }
    }

    #pragma unroll
    for (int i2 = 0; i2 < 4; i2++) {
        const int r0 = q0 + ty * 8 + 2 * i2;
        const float il0 = 1.0f / l_r[2 * i2];
        const float il1 = 1.0f / l_r[2 * i2 + 1];
        float v0[4], v1[4];
        #pragma unroll
        for (int j = 0; j < 4; j++) {
            upk2(o2[i2][j], v0[j], v1[j]);
            v0[j] *= il0; v1[j] *= il1;
        }
        *(float4*)&out[((size_t)b * SEQ + r0) * HD + tx * 4]     = make_float4(v0[0], v0[1], v0[2], v0[3]);
        *(float4*)&out[((size_t)b * SEQ + r0 + 1) * HD + tx * 4] = make_float4(v1[0], v1[1], v1[2], v1[3]);
    }
}

extern "C" void kernel_launch(void* const* d_in, const int* in_sizes, int n_in,
                              void* d_out, int out_size)
{
    const float* x  = (const float*)d_in[0];
    const float* Wq = (const float*)d_in[1];
    const float* Wk = (const float*)d_in[2];
    const float* Wv = (const float*)d_in[3];
    float* out = (float*)d_out;

    rope_table_kernel<<<(SEQ * 32 + 255) / 256, 256>>>();

    dim3 g1((BSZ * SEQ) / 128, 3);
    qkv_rope_kernel<<<g1, 256>>>(x, Wq, Wk, Wv);

    const int smem = (2 * 64 * QP + 2 * 64 * KP) * (int)sizeof(float);
    cudaFuncSetAttribute(attn_kernel, cudaFuncAttributeMaxDynamicSharedMemorySize, smem);
    dim3 g2(SEQ / 64, BSZ);
    attn_kernel<<<g2, 128, smem>>>(out);
}

// round 6
// speedup vs baseline: 2.9998x; 1.4687x over previous
#include <cuda_runtime.h>
#include <math.h>

#define BSZ 32
#define SEQ 1024
#define EMB 768
#define HD  64

typedef unsigned long long ull;
typedef unsigned int uint32;

// ---- packed f32x2 helpers ----
__device__ __forceinline__ ull pk2(float lo, float hi) {
    ull r; asm("mov.b64 %0, {%1, %2};" : "=l"(r) : "f"(lo), "f"(hi)); return r;
}

// ---- tf32 mma helpers ----
__device__ __forceinline__ uint32 f2tf32(float x) {
    uint32 y; asm("cvt.rna.tf32.f32 %0, %1;" : "=r"(y) : "f"(x)); return y;
}
__device__ __forceinline__ void mma_tf32(float c[4],
    uint32 a0, uint32 a1, uint32 a2, uint32 a3, uint32 b0, uint32 b1)
{
    asm volatile(
        "mma.sync.aligned.m16n8k8.row.col.f32.tf32.tf32.f32 "
        "{%0,%1,%2,%3}, {%4,%5,%6,%7}, {%8,%9}, {%0,%1,%2,%3};"
        : "+f"(c[0]), "+f"(c[1]), "+f"(c[2]), "+f"(c[3])
        : "r"(a0), "r"(a1), "r"(a2), "r"(a3), "r"(b0), "r"(b1));
}

// scratch (static device arrays — no allocation)
__device__ float g_q[BSZ * SEQ * HD];
__device__ float g_k[BSZ * SEQ * HD];
__device__ float g_v[BSZ * SEQ * HD];
__device__ float g_cos[SEQ * 32];
__device__ float g_sin[SEQ * 32];

// ---------------------------------------------------------------------------
// Kernel 0: RoPE cos/sin table
// ---------------------------------------------------------------------------
__global__ void rope_table_kernel()
{
    const int t = blockIdx.x * blockDim.x + threadIdx.x;
    if (t >= SEQ * 32) return;
    const int pos = t >> 5;
    const int pr  = t & 31;
    const float theta = expf((float)pr * -0.5756462732485114f);
    float sn, cs;
    sincosf((float)pos * theta, &sn, &cs);
    g_cos[t] = cs;
    g_sin[t] = sn;
}

// ---------------------------------------------------------------------------
// Kernel 1: QKV projection via mma.sync tf32 + RoPE epilogue (as R5)
// ---------------------------------------------------------------------------
#define SSTR 36

__global__ __launch_bounds__(256) void qkv_rope_kernel(
    const float* __restrict__ x,
    const float* __restrict__ Wq,
    const float* __restrict__ Wk,
    const float* __restrict__ Wv)
{
    const int which = blockIdx.y;
    const float* __restrict__ W = (which == 0) ? Wq : ((which == 1) ? Wk : Wv);
    float* __restrict__ outp    = (which == 0) ? g_q : ((which == 1) ? g_k : g_v);

    const int m0 = blockIdx.x * 128;

    __shared__ uint32 xs[128 * SSTR];
    __shared__ uint32 ws[64 * SSTR];

    const int tid    = threadIdx.x;
    const int lane   = tid & 31;
    const int wid    = tid >> 5;
    const int warp_m = wid & 3;
    const int warp_n = wid >> 2;
    const int lr = lane >> 2;
    const int lc = lane & 3;

    float c[2][4][4];
    #pragma unroll
    for (int mt = 0; mt < 2; mt++)
        #pragma unroll
        for (int nt = 0; nt < 4; nt++)
            #pragma unroll
            for (int r = 0; r < 4; r++) c[mt][nt][r] = 0.f;

    for (int e0 = 0; e0 < EMB; e0 += 32) {
        __syncthreads();
        #pragma unroll
        for (int q = 0; q < 4; q++) {
            const int p = tid + q * 256;
            const int row = p >> 3, kq = p & 7;
            float4 t = *(const float4*)&x[(size_t)(m0 + row) * EMB + e0 + kq * 4];
            uint32* d = &xs[row * SSTR + kq * 4];
            d[0] = f2tf32(t.x); d[1] = f2tf32(t.y); d[2] = f2tf32(t.z); d[3] = f2tf32(t.w);
        }
        #pragma unroll
        for (int q = 0; q < 2; q++) {
            const int p = tid + q * 256;
            const int row = p >> 3, kq = p & 7;
            float4 t = *(const float4*)&W[(size_t)row * EMB + e0 + kq * 4];
            uint32* d = &ws[row * SSTR + kq * 4];
            d[0] = f2tf32(t.x); d[1] = f2tf32(t.y); d[2] = f2tf32(t.z); d[3] = f2tf32(t.w);
        }
        __syncthreads();

        #pragma unroll
        for (int ks = 0; ks < 4; ks++) {
            const int k0 = ks * 8;
            uint32 a[2][4];
            #pragma unroll
            for (int mt = 0; mt < 2; mt++) {
                const int rb = warp_m * 32 + mt * 16 + lr;
                a[mt][0] = xs[rb * SSTR + k0 + lc];
                a[mt][1] = xs[(rb + 8) * SSTR + k0 + lc];
                a[mt][2] = xs[rb * SSTR + k0 + lc + 4];
                a[mt][3] = xs[(rb + 8) * SSTR + k0 + lc + 4];
            }
            uint32 bb[4][2];
            #pragma unroll
            for (int nt = 0; nt < 4; nt++) {
                const int nb = warp_n * 32 + nt * 8 + lr;
                bb[nt][0] = ws[nb * SSTR + k0 + lc];
                bb[nt][1] = ws[nb * SSTR + k0 + lc + 4];
            }
            #pragma unroll
            for (int mt = 0; mt < 2; mt++)
                #pragma unroll
                for (int nt = 0; nt < 4; nt++)
                    mma_tf32(c[mt][nt], a[mt][0], a[mt][1], a[mt][2], a[mt][3],
                             bb[nt][0], bb[nt][1]);
        }
    }

    if (which < 2) {
        #pragma unroll
        for (int mt = 0; mt < 2; mt++) {
            const int r0 = m0 + warp_m * 32 + mt * 16 + lr;
            const int r1 = r0 + 8;
            const int p0 = r0 & (SEQ - 1);
            const int p1 = r1 & (SEQ - 1);
            #pragma unroll
            for (int nt = 0; nt < 4; nt++) {
                const int d0   = warp_n * 32 + nt * 8 + 2 * lc;
                const int pair = d0 >> 1;
                {
                    const float cs = g_cos[p0 * 32 + pair];
                    const float sn = g_sin[p0 * 32 + pair];
                    const float av = c[mt][nt][0], bv = c[mt][nt][1];
                    *(ull*)&outp[(size_t)r0 * HD + d0] = pk2(av * cs - bv * sn, bv * cs + av * sn);
                }
                {
                    const float cs = g_cos[p1 * 32 + pair];
                    const float sn = g_sin[p1 * 32 + pair];
                    const float av = c[mt][nt][2], bv = c[mt][nt][3];
                    *(ull*)&outp[(size_t)r1 * HD + d0] = pk2(av * cs - bv * sn, bv * cs + av * sn);
                }
            }
        }
    } else {
        #pragma unroll
        for (int mt = 0; mt < 2; mt++) {
            const int r0 = m0 + warp_m * 32 + mt * 16 + lr;
            #pragma unroll
            for (int nt = 0; nt < 4; nt++) {
                const int d0 = warp_n * 32 + nt * 8 + 2 * lc;
                *(ull*)&outp[(size_t)r0 * HD + d0]       = pk2(c[mt][nt][0], c[mt][nt][1]);
                *(ull*)&outp[(size_t)(r0 + 8) * HD + d0] = pk2(c[mt][nt][2], c[mt][nt][3]);
            }
        }
    }
}

// ---------------------------------------------------------------------------
// Kernel 2: causal flash attention — tf32 mma.sync for S=QK^T and O+=PV.
//   128 thr / 4 warps; warp w owns q-rows [w*16, w*16+16).
//   Pads: Qs/Ks/Ps = 68 (bank 4*lr+lc), Vs = 72 (bank 8*lc+lr) — conflict-free.
// ---------------------------------------------------------------------------
#define AQP 68
#define AVP 72

__global__ __launch_bounds__(128) void attn_kernel(float* __restrict__ out)
{
    extern __shared__ uint32 smu[];
    uint32* Qs = smu;                 // [64][68] tf32
    uint32* Ks = Qs + 64 * AQP;       // [64][68] tf32
    uint32* Ps = Ks + 64 * AQP;       // [64][68] tf32
    uint32* Vs = Ps + 64 * AQP;       // [64][72] tf32

    const int b  = blockIdx.y;
    const int qt = (SEQ / 64 - 1) - blockIdx.x;   // largest work first
    const int q0 = qt * 64;

    const float* __restrict__ qp = g_q + ((size_t)b * SEQ + q0) * HD;
    const float* __restrict__ kp = g_k + (size_t)b * SEQ * HD;
    const float* __restrict__ vp = g_v + (size_t)b * SEQ * HD;

    const int tid  = threadIdx.x;
    const int lane = tid & 31;
    const int w    = tid >> 5;      // warp id: q-rows w*16..w*16+15
    const int lr   = lane >> 2;     // 0..7
    const int lc   = lane & 3;      // 0..3

    // load Q tile (tf32)
    #pragma unroll
    for (int q = 0; q < 8; q++) {
        const int p = tid + q * 128;          // 0..1023 float4s
        float4 t = ((const float4*)qp)[p];
        const int r = p >> 4, h = (p & 15) * 4;
        uint32* d = &Qs[r * AQP + h];
        d[0] = f2tf32(t.x); d[1] = f2tf32(t.y); d[2] = f2tf32(t.z); d[3] = f2tf32(t.w);
    }

    float m_r[2] = {-1e30f, -1e30f};
    float l_r[2] = {0.f, 0.f};
    float o[8][4];
    #pragma unroll
    for (int nt = 0; nt < 8; nt++)
        #pragma unroll
        for (int r = 0; r < 4; r++) o[nt][r] = 0.f;

    const float scale = 0.03608439182435161f;   // 768^-0.5
    const int ntiles = qt + 1;
    const int row0 = q0 + w * 16 + lr;          // global q row (c0/c1)
    const int row1 = row0 + 8;                  // global q row (c2/c3)

    for (int t = 0; t < ntiles; t++) {
        const int k0 = t * 64;
        __syncthreads();

        // stage K,V tiles (tf32)
        #pragma unroll
        for (int q = 0; q < 8; q++) {
            const int p = tid + q * 128;
            float4 tk = ((const float4*)(kp + (size_t)k0 * HD))[p];
            float4 tv = ((const float4*)(vp + (size_t)k0 * HD))[p];
            const int r = p >> 4, h = (p & 15) * 4;
            uint32* dk = &Ks[r * AQP + h];
            dk[0] = f2tf32(tk.x); dk[1] = f2tf32(tk.y); dk[2] = f2tf32(tk.z); dk[3] = f2tf32(tk.w);
            uint32* dv = &Vs[r * AVP + h];
            dv[0] = f2tf32(tv.x); dv[1] = f2tf32(tv.y); dv[2] = f2tf32(tv.z); dv[3] = f2tf32(tv.w);
        }
        __syncthreads();

        // ---- S = Q K^T ----
        float s[8][4];
        #pragma unroll
        for (int nt = 0; nt < 8; nt++)
            #pragma unroll
            for (int r = 0; r < 4; r++) s[nt][r] = 0.f;

        #pragma unroll
        for (int ks = 0; ks < 8; ks++) {
            const int kk = ks * 8;
            const int rb = w * 16 + lr;
            const uint32 a0 = Qs[rb * AQP + kk + lc];
            const uint32 a1 = Qs[(rb + 8) * AQP + kk + lc];
            const uint32 a2 = Qs[rb * AQP + kk + lc + 4];
            const uint32 a3 = Qs[(rb + 8) * AQP + kk + lc + 4];
            #pragma unroll
            for (int nt = 0; nt < 8; nt++) {
                const int nb = nt * 8 + lr;
                const uint32 b0 = Ks[nb * AQP + kk + lc];
                const uint32 b1 = Ks[nb * AQP + kk + lc + 4];
                mma_tf32(s[nt], a0, a1, a2, a3, b0, b1);
            }
        }

        // scale + causal mask
        const bool diag = (k0 == q0);
        #pragma unroll
        for (int nt = 0; nt < 8; nt++) {
            const int col = k0 + nt * 8 + 2 * lc;
            #pragma unroll
            for (int r = 0; r < 4; r++) {
                float sv = s[nt][r] * scale;
                if (diag) {
                    const int gr = (r < 2) ? row0 : row1;
                    const int gc = col + (r & 1);
                    if (gc > gr) sv = -1e30f;
                }
                s[nt][r] = sv;
            }
        }

        // ---- online softmax (2 rows/thread; reduce over 4-lane lc group) ----
        float alpha[2];
        #pragma unroll
        for (int h = 0; h < 2; h++) {
            float rm = -1e30f;
            #pragma unroll
            for (int nt = 0; nt < 8; nt++)
                rm = fmaxf(rm, fmaxf(s[nt][2 * h], s[nt][2 * h + 1]));
            rm = fmaxf(rm, __shfl_xor_sync(0xffffffffu, rm, 1));
            rm = fmaxf(rm, __shfl_xor_sync(0xffffffffu, rm, 2));
            const float mnew = fmaxf(m_r[h], rm);
            alpha[h] = __expf(m_r[h] - mnew);
            m_r[h] = mnew;

            float rs = 0.f;
            #pragma unroll
            for (int nt = 0; nt < 8; nt++) {
                const float p0 = __expf(s[nt][2 * h]     - mnew);
                const float p1 = __expf(s[nt][2 * h + 1] - mnew);
                s[nt][2 * h] = p0; s[nt][2 * h + 1] = p1;
                rs += p0 + p1;
            }
            rs += __shfl_xor_sync(0xffffffffu, rs, 1);
            rs += __shfl_xor_sync(0xffffffffu, rs, 2);
            l_r[h] = l_r[h] * alpha[h] + rs;
        }

        // rescale O, stage P (tf32) to smem
        #pragma unroll
        for (int nt = 0; nt < 8; nt++) {
            o[nt][0] *= alpha[0]; o[nt][1] *= alpha[0];
            o[nt][2] *= alpha[1]; o[nt][3] *= alpha[1];
            const int cb = nt * 8 + 2 * lc;
            const int r0 = w * 16 + lr;
            Ps[r0 * AQP + cb]           = f2tf32(s[nt][0]);
            Ps[r0 * AQP + cb + 1]       = f2tf32(s[nt][1]);
            Ps[(r0 + 8) * AQP + cb]     = f2tf32(s[nt][2]);
            Ps[(r0 + 8) * AQP + cb + 1] = f2tf32(s[nt][3]);
        }
        __syncwarp();   // Ps rows are warp-private (w*16..+16) — warp sync suffices

        // ---- O += P V ----
        #pragma unroll
        for (int ks = 0; ks < 8; ks++) {
            const int kk = ks * 8;
            const int rb = w * 16 + lr;
            const uint32 a0 = Ps[rb * AQP + kk + lc];
            const uint32 a1 = Ps[(rb + 8) * AQP + kk + lc];
            const uint32 a2 = Ps[rb * AQP + kk + lc + 4];
            const uint32 a3 = Ps[(rb + 8) * AQP + kk + lc + 4];
            #pragma unroll
            for (int nt = 0; nt < 8; nt++) {
                const int nb = nt * 8 + lr;
                const uint32 b0 = Vs[(kk + lc) * AVP + nb];
                const uint32 b1 = Vs[(kk + lc + 4) * AVP + nb];
                mma_tf32(o[nt], a0, a1, a2, a3, b0, b1);
            }
        }
    }

    const float il0 = 1.0f / l_r[0];
    const float il1 = 1.0f / l_r[1];
    #pragma unroll
    for (int nt = 0; nt < 8; nt++) {
        const int d0 = nt * 8 + 2 * lc;
        *(ull*)&out[((size_t)b * SEQ + row0) * HD + d0] = pk2(o[nt][0] * il0, o[nt][1] * il0);
        *(ull*)&out[((size_t)b * SEQ + row1) * HD + d0] = pk2(o[nt][2] * il1, o[nt][3] * il1);
    }
}

extern "C" void kernel_launch(void* const* d_in, const int* in_sizes, int n_in,
                              void* d_out, int out_size)
{
    const float* x  = (const float*)d_in[0];
    const float* Wq = (const float*)d_in[1];
    const float* Wk = (const float*)d_in[2];
    const float* Wv = (const float*)d_in[3];
    float* out = (float*)d_out;

    rope_table_kernel<<<(SEQ * 32 + 255) / 256, 256>>>();

    dim3 g1((BSZ * SEQ) / 128, 3);
    qkv_rope_kernel<<<g1, 256>>>(x, Wq, Wk, Wv);

    const int smem = (3 * 64 * AQP + 64 * AVP) * (int)sizeof(uint32);   // 70656 B
    cudaFuncSetAttribute(attn_kernel, cudaFuncAttributeMaxDynamicSharedMemorySize, smem);
    dim3 g2(SEQ / 64, BSZ);
    attn_kernel<<<g2, 128, smem>>>(out);
}

// round 7
// speedup vs baseline: 3.0233x; 1.0078x over previous
#include <cuda_runtime.h>
#include <math.h>

#define BSZ 32
#define SEQ 1024
#define EMB 768
#define HD  64

typedef unsigned long long ull;
typedef unsigned int uint32;

__device__ __forceinline__ ull pk2(float lo, float hi) {
    ull r; asm("mov.b64 %0, {%1, %2};" : "=l"(r) : "f"(lo), "f"(hi)); return r;
}
__device__ __forceinline__ uint32 f2tf32(float x) {
    uint32 y; asm("cvt.rna.tf32.f32 %0, %1;" : "=r"(y) : "f"(x)); return y;
}
__device__ __forceinline__ void mma_tf32(float c[4],
    uint32 a0, uint32 a1, uint32 a2, uint32 a3, uint32 b0, uint32 b1)
{
    asm volatile(
        "mma.sync.aligned.m16n8k8.row.col.f32.tf32.tf32.f32 "
        "{%0,%1,%2,%3}, {%4,%5,%6,%7}, {%8,%9}, {%0,%1,%2,%3};"
        : "+f"(c[0]), "+f"(c[1]), "+f"(c[2]), "+f"(c[3])
        : "r"(a0), "r"(a1), "r"(a2), "r"(a3), "r"(b0), "r"(b1));
}

__device__ float g_q[BSZ * SEQ * HD];
__device__ float g_k[BSZ * SEQ * HD];
__device__ float g_v[BSZ * SEQ * HD];
__device__ float g_cos[SEQ * 32];
__device__ float g_sin[SEQ * 32];

// ---------------------------------------------------------------------------
// Kernel 0: RoPE cos/sin table
// ---------------------------------------------------------------------------
__global__ void rope_table_kernel()
{
    const int t = blockIdx.x * blockDim.x + threadIdx.x;
    if (t >= SEQ * 32) return;
    const int pos = t >> 5;
    const int pr  = t & 31;
    const float theta = expf((float)pr * -0.5756462732485114f);
    float sn, cs;
    sincosf((float)pos * theta, &sn, &cs);
    g_cos[t] = cs;
    g_sin[t] = sn;
}

// ---------------------------------------------------------------------------
// Kernel 1: QKV projection (tf32 mma, double-buffered + reg prefetch) + RoPE
//   grid = (3, 256): which fastest -> 3 blocks sharing one x tile co-resident.
// ---------------------------------------------------------------------------
#define SSTR 36

__global__ __launch_bounds__(256) void qkv_rope_kernel(
    const float* __restrict__ x,
    const float* __restrict__ Wq,
    const float* __restrict__ Wk,
    const float* __restrict__ Wv)
{
    const int which = blockIdx.x;
    const float* __restrict__ W = (which == 0) ? Wq : ((which == 1) ? Wk : Wv);
    float* __restrict__ outp    = (which == 0) ? g_q : ((which == 1) ? g_k : g_v);

    const int m0 = blockIdx.y * 128;

    __shared__ uint32 xs[2][128 * SSTR];
    __shared__ uint32 ws[2][64 * SSTR];

    const int tid    = threadIdx.x;
    const int lane   = tid & 31;
    const int wid    = tid >> 5;
    const int warp_m = wid & 3;
    const int warp_n = wid >> 2;
    const int lr = lane >> 2;
    const int lc = lane & 3;

    float4 rx[4], rw[2];
    const int xrow = tid >> 3, xkq = (tid & 7) * 4;   // + q*32 rows

    float c[2][4][4];
    #pragma unroll
    for (int mt = 0; mt < 2; mt++)
        #pragma unroll
        for (int nt = 0; nt < 4; nt++)
            #pragma unroll
            for (int r = 0; r < 4; r++) c[mt][nt][r] = 0.f;

    // prologue: chunk 0 -> regs -> buf 0
    #pragma unroll
    for (int q = 0; q < 4; q++)
        rx[q] = *(const float4*)&x[(size_t)(m0 + xrow + q * 32) * EMB + xkq];
    #pragma unroll
    for (int q = 0; q < 2; q++)
        rw[q] = *(const float4*)&W[(size_t)(xrow + q * 32) * EMB + xkq];
    #pragma unroll
    for (int q = 0; q < 4; q++) {
        uint32* d = &xs[0][(xrow + q * 32) * SSTR + xkq];
        d[0] = f2tf32(rx[q].x); d[1] = f2tf32(rx[q].y); d[2] = f2tf32(rx[q].z); d[3] = f2tf32(rx[q].w);
    }
    #pragma unroll
    for (int q = 0; q < 2; q++) {
        uint32* d = &ws[0][(xrow + q * 32) * SSTR + xkq];
        d[0] = f2tf32(rw[q].x); d[1] = f2tf32(rw[q].y); d[2] = f2tf32(rw[q].z); d[3] = f2tf32(rw[q].w);
    }
    __syncthreads();

    const int NCH = EMB / 32;   // 24
    for (int ec = 0; ec < NCH; ec++) {
        const int cur = ec & 1;
        const bool more = (ec + 1 < NCH);
        if (more) {
            const int e1 = (ec + 1) * 32;
            #pragma unroll
            for (int q = 0; q < 4; q++)
                rx[q] = *(const float4*)&x[(size_t)(m0 + xrow + q * 32) * EMB + e1 + xkq];
            #pragma unroll
            for (int q = 0; q < 2; q++)
                rw[q] = *(const float4*)&W[(size_t)(xrow + q * 32) * EMB + e1 + xkq];
        }

        #pragma unroll
        for (int ks = 0; ks < 4; ks++) {
            const int k0 = ks * 8;
            uint32 a[2][4];
            #pragma unroll
            for (int mt = 0; mt < 2; mt++) {
                const int rb = warp_m * 32 + mt * 16 + lr;
                a[mt][0] = xs[cur][rb * SSTR + k0 + lc];
                a[mt][1] = xs[cur][(rb + 8) * SSTR + k0 + lc];
                a[mt][2] = xs[cur][rb * SSTR + k0 + lc + 4];
                a[mt][3] = xs[cur][(rb + 8) * SSTR + k0 + lc + 4];
            }
            uint32 bb[4][2];
            #pragma unroll
            for (int nt = 0; nt < 4; nt++) {
                const int nb = warp_n * 32 + nt * 8 + lr;
                bb[nt][0] = ws[cur][nb * SSTR + k0 + lc];
                bb[nt][1] = ws[cur][nb * SSTR + k0 + lc + 4];
            }
            #pragma unroll
            for (int mt = 0; mt < 2; mt++)
                #pragma unroll
                for (int nt = 0; nt < 4; nt++)
                    mma_tf32(c[mt][nt], a[mt][0], a[mt][1], a[mt][2], a[mt][3],
                             bb[nt][0], bb[nt][1]);
        }

        if (more) {
            const int nxt = cur ^ 1;
            #pragma unroll
            for (int q = 0; q < 4; q++) {
                uint32* d = &xs[nxt][(xrow + q * 32) * SSTR + xkq];
                d[0] = f2tf32(rx[q].x); d[1] = f2tf32(rx[q].y); d[2] = f2tf32(rx[q].z); d[3] = f2tf32(rx[q].w);
            }
            #pragma unroll
            for (int q = 0; q < 2; q++) {
                uint32* d = &ws[nxt][(xrow + q * 32) * SSTR + xkq];
                d[0] = f2tf32(rw[q].x); d[1] = f2tf32(rw[q].y); d[2] = f2tf32(rw[q].z); d[3] = f2tf32(rw[q].w);
            }
            __syncthreads();
        }
    }

    if (which < 2) {
        #pragma unroll
        for (int mt = 0; mt < 2; mt++) {
            const int r0 = m0 + warp_m * 32 + mt * 16 + lr;
            const int r1 = r0 + 8;
            const int p0 = r0 & (SEQ - 1);
            const int p1 = r1 & (SEQ - 1);
            #pragma unroll
            for (int nt = 0; nt < 4; nt++) {
                const int d0   = warp_n * 32 + nt * 8 + 2 * lc;
                const int pair = d0 >> 1;
                {
                    const float cs = g_cos[p0 * 32 + pair];
                    const float sn = g_sin[p0 * 32 + pair];
                    const float av = c[mt][nt][0], bv = c[mt][nt][1];
                    *(ull*)&outp[(size_t)r0 * HD + d0] = pk2(av * cs - bv * sn, bv * cs + av * sn);
                }
                {
                    const float cs = g_cos[p1 * 32 + pair];
                    const float sn = g_sin[p1 * 32 + pair];
                    const float av = c[mt][nt][2], bv = c[mt][nt][3];
                    *(ull*)&outp[(size_t)r1 * HD + d0] = pk2(av * cs - bv * sn, bv * cs + av * sn);
                }
            }
        }
    } else {
        #pragma unroll
        for (int mt = 0; mt < 2; mt++) {
            const int r0 = m0 + warp_m * 32 + mt * 16 + lr;
            #pragma unroll
            for (int nt = 0; nt < 4; nt++) {
                const int d0 = warp_n * 32 + nt * 8 + 2 * lc;
                *(ull*)&outp[(size_t)r0 * HD + d0]       = pk2(c[mt][nt][0], c[mt][nt][1]);
                *(ull*)&outp[(size_t)(r0 + 8) * HD + d0] = pk2(c[mt][nt][2], c[mt][nt][3]);
            }
        }
    }
}

// ---------------------------------------------------------------------------
// Kernel 2: causal flash attention — tf32 mma, double-buffered K/V + prefetch.
// ---------------------------------------------------------------------------
#define AQP 68
#define AVP 72

__global__ __launch_bounds__(128) void attn_kernel(float* __restrict__ out)
{
    extern __shared__ uint32 smu[];
    uint32* Qs = smu;                     // [64][68]
    uint32* Ps = Qs + 64 * AQP;           // [64][68]
    uint32* Ks = Ps + 64 * AQP;           // [2][64][68]
    uint32* Vs = Ks + 2 * 64 * AQP;       // [2][64][72]

    const int b  = blockIdx.y;
    const int qt = (SEQ / 64 - 1) - blockIdx.x;   // largest work first
    const int q0 = qt * 64;

    const float* __restrict__ qp = g_q + ((size_t)b * SEQ + q0) * HD;
    const float* __restrict__ kp = g_k + (size_t)b * SEQ * HD;
    const float* __restrict__ vp = g_v + (size_t)b * SEQ * HD;

    const int tid  = threadIdx.x;
    const int lane = tid & 31;
    const int w    = tid >> 5;
    const int lr   = lane >> 2;
    const int lc   = lane & 3;

    float4 rk[8], rv[8];

    // prologue: K/V tile 0 -> regs; Q tile -> smem
    #pragma unroll
    for (int q = 0; q < 8; q++) {
        const int p = tid + q * 128;
        rk[q] = ((const float4*)kp)[p];
        rv[q] = ((const float4*)vp)[p];
    }
    #pragma unroll
    for (int q = 0; q < 8; q++) {
        const int p = tid + q * 128;
        float4 t = ((const float4*)qp)[p];
        const int r = p >> 4, h = (p & 15) * 4;
        uint32* d = &Qs[r * AQP + h];
        d[0] = f2tf32(t.x); d[1] = f2tf32(t.y); d[2] = f2tf32(t.z); d[3] = f2tf32(t.w);
    }
    #pragma unroll
    for (int q = 0; q < 8; q++) {
        const int p = tid + q * 128;
        const int r = p >> 4, h = (p & 15) * 4;
        uint32* dk = &Ks[r * AQP + h];
        dk[0] = f2tf32(rk[q].x); dk[1] = f2tf32(rk[q].y); dk[2] = f2tf32(rk[q].z); dk[3] = f2tf32(rk[q].w);
        uint32* dv = &Vs[r * AVP + h];
        dv[0] = f2tf32(rv[q].x); dv[1] = f2tf32(rv[q].y); dv[2] = f2tf32(rv[q].z); dv[3] = f2tf32(rv[q].w);
    }
    __syncthreads();

    float m_r[2] = {-1e30f, -1e30f};
    float l_r[2] = {0.f, 0.f};
    float o[8][4];
    #pragma unroll
    for (int nt = 0; nt < 8; nt++)
        #pragma unroll
        for (int r = 0; r < 4; r++) o[nt][r] = 0.f;

    // scale * log2(e): softmax computed in log2 domain (exp2f = raw MUFU.EX2)
    const float sc2 = 0.03608439182435161f * 1.4426950408889634f;
    const int ntiles = qt + 1;
    const int row0 = q0 + w * 16 + lr;
    const int row1 = row0 + 8;

    for (int t = 0; t < ntiles; t++) {
        const int cur  = t & 1;
        const bool more = (t + 1 < ntiles);
        uint32* Kc = Ks + cur * 64 * AQP;
        uint32* Vc = Vs + cur * 64 * AVP;

        if (more) {
            const int k1 = (t + 1) * 64;
            #pragma unroll
            for (int q = 0; q < 8; q++) {
                const int p = tid + q * 128;
                rk[q] = ((const float4*)(kp + (size_t)k1 * HD))[p];
                rv[q] = ((const float4*)(vp + (size_t)k1 * HD))[p];
            }
        }

        // ---- S = Q K^T ----
        float s[8][4];
        #pragma unroll
        for (int nt = 0; nt < 8; nt++)
            #pragma unroll
            for (int r = 0; r < 4; r++) s[nt][r] = 0.f;

        #pragma unroll
        for (int ks = 0; ks < 8; ks++) {
            const int kk = ks * 8;
            const int rb = w * 16 + lr;
            const uint32 a0 = Qs[rb * AQP + kk + lc];
            const uint32 a1 = Qs[(rb + 8) * AQP + kk + lc];
            const uint32 a2 = Qs[rb * AQP + kk + lc + 4];
            const uint32 a3 = Qs[(rb + 8) * AQP + kk + lc + 4];
            #pragma unroll
            for (int nt = 0; nt < 8; nt++) {
                const int nb = nt * 8 + lr;
                const uint32 b0 = Kc[nb * AQP + kk + lc];
                const uint32 b1 = Kc[nb * AQP + kk + lc + 4];
                mma_tf32(s[nt], a0, a1, a2, a3, b0, b1);
            }
        }

        // scale (log2 domain) + causal mask
        const bool diag = (t * 64 == q0);
        #pragma unroll
        for (int nt = 0; nt < 8; nt++) {
            const int col = t * 64 + nt * 8 + 2 * lc;
            #pragma unroll
            for (int r = 0; r < 4; r++) {
                float sv = s[nt][r] * sc2;
                if (diag) {
                    const int gr = (r < 2) ? row0 : row1;
                    const int gc = col + (r & 1);
                    if (gc > gr) sv = -1e30f;
                }
                s[nt][r] = sv;
            }
        }

        // ---- online softmax ----
        float alpha[2];
        #pragma unroll
        for (int h = 0; h < 2; h++) {
            float rm = -1e30f;
            #pragma unroll
            for (int nt = 0; nt < 8; nt++)
                rm = fmaxf(rm, fmaxf(s[nt][2 * h], s[nt][2 * h + 1]));
            rm = fmaxf(rm, __shfl_xor_sync(0xffffffffu, rm, 1));
            rm = fmaxf(rm, __shfl_xor_sync(0xffffffffu, rm, 2));
            const float mnew = fmaxf(m_r[h], rm);
            alpha[h] = exp2f(m_r[h] - mnew);
            m_r[h] = mnew;

            float rs = 0.f;
            #pragma unroll
            for (int nt = 0; nt < 8; nt++) {
                const float p0 = exp2f(s[nt][2 * h]     - mnew);
                const float p1 = exp2f(s[nt][2 * h + 1] - mnew);
                s[nt][2 * h] = p0; s[nt][2 * h + 1] = p1;
                rs += p0 + p1;
            }
            rs += __shfl_xor_sync(0xffffffffu, rs, 1);
            rs += __shfl_xor_sync(0xffffffffu, rs, 2);
            l_r[h] = l_r[h] * alpha[h] + rs;
        }

        // rescale O, stage P (warp-private rows)
        #pragma unroll
        for (int nt = 0; nt < 8; nt++) {
            o[nt][0] *= alpha[0]; o[nt][1] *= alpha[0];
            o[nt][2] *= alpha[1]; o[nt][3] *= alpha[1];
            const int cb = nt * 8 + 2 * lc;
            const int r0 = w * 16 + lr;
            Ps[r0 * AQP + cb]           = f2tf32(s[nt][0]);
            Ps[r0 * AQP + cb + 1]       = f2tf32(s[nt][1]);
            Ps[(r0 + 8) * AQP + cb]     = f2tf32(s[nt][2]);
            Ps[(r0 + 8) * AQP + cb + 1] = f2tf32(s[nt][3]);
        }
        __syncwarp();

        // ---- O += P V ----
        #pragma unroll
        for (int ks = 0; ks < 8; ks++) {
            const int kk = ks * 8;
            const int rb = w * 16 + lr;
            const uint32 a0 = Ps[rb * AQP + kk + lc];
            const uint32 a1 = Ps[(rb + 8) * AQP + kk + lc];
            const uint32 a2 = Ps[rb * AQP + kk + lc + 4];
            const uint32 a3 = Ps[(rb + 8) * AQP + kk + lc + 4];
            #pragma unroll
            for (int nt = 0; nt < 8; nt++) {
                const int nb = nt * 8 + lr;
                const uint32 b0 = Vc[(kk + lc) * AVP + nb];
                const uint32 b1 = Vc[(kk + lc + 4) * AVP + nb];
                mma_tf32(o[nt], a0, a1, a2, a3, b0, b1);
            }
        }

        if (more) {
            const int nxt = cur ^ 1;
            uint32* Kn = Ks + nxt * 64 * AQP;
            uint32* Vn = Vs + nxt * 64 * AVP;
            #pragma unroll
            for (int q = 0; q < 8; q++) {
                const int p = tid + q * 128;
                const int r = p >> 4, h = (p & 15) * 4;
                uint32* dk = &Kn[r * AQP + h];
                dk[0] = f2tf32(rk[q].x); dk[1] = f2tf32(rk[q].y); dk[2] = f2tf32(rk[q].z); dk[3] = f2tf32(rk[q].w);
                uint32* dv = &Vn[r * AVP + h];
                dv[0] = f2tf32(rv[q].x); dv[1] = f2tf32(rv[q].y); dv[2] = f2tf32(rv[q].z); dv[3] = f2tf32(rv[q].w);
            }
            __syncthreads();
        }
    }

    const float il0 = 1.0f / l_r[0];
    const float il1 = 1.0f / l_r[1];
    #pragma unroll
    for (int nt = 0; nt < 8; nt++) {
        const int d0 = nt * 8 + 2 * lc;
        *(ull*)&out[((size_t)b * SEQ + row0) * HD + d0] = pk2(o[nt][0] * il0, o[nt][1] * il0);
        *(ull*)&out[((size_t)b * SEQ + row1) * HD + d0] = pk2(o[nt][2] * il1, o[nt][3] * il1);
    }
}

extern "C" void kernel_launch(void* const* d_in, const int* in_sizes, int n_in,
                              void* d_out, int out_size)
{
    const float* x  = (const float*)d_in[0];
    const float* Wq = (const float*)d_in[1];
    const float* Wk = (const float*)d_in[2];
    const float* Wv = (const float*)d_in[3];
    float* out = (float*)d_out;

    rope_table_kernel<<<(SEQ * 32 + 255) / 256, 256>>>();

    dim3 g1(3, (BSZ * SEQ) / 128);
    qkv_rope_kernel<<<g1, 256>>>(x, Wq, Wk, Wv);

    const int smem = (2 * 64 * AQP + 2 * 64 * AQP + 2 * 64 * AVP) * (int)sizeof(uint32); // 106496 B
    cudaFuncSetAttribute(attn_kernel, cudaFuncAttributeMaxDynamicSharedMemorySize, smem);
    dim3 g2(SEQ / 64, BSZ);
    attn_kernel<<<g2, 128, smem>>>(out);
}

// round 8
// speedup vs baseline: 4.1707x; 1.3795x over previous
#include <cuda_runtime.h>
#include <cuda_fp16.h>
#include <math.h>

#define BSZ 32
#define SEQ 1024
#define EMB 768
#define HD  64

typedef unsigned long long ull;
typedef unsigned int uint32;

__device__ __forceinline__ ull pk2(float lo, float hi) {
    ull r; asm("mov.b64 %0, {%1, %2};" : "=l"(r) : "f"(lo), "f"(hi)); return r;
}
// pack two fp32 -> f16x2 (lo in low half)
__device__ __forceinline__ uint32 ph2(float lo, float hi) {
    uint32 r; asm("cvt.rn.f16x2.f32 %0, %1, %2;" : "=r"(r) : "f"(hi), "f"(lo)); return r;
}
__device__ __forceinline__ void mma_f16(float c[4],
    uint32 a0, uint32 a1, uint32 a2, uint32 a3, uint32 b0, uint32 b1)
{
    asm volatile(
        "mma.sync.aligned.m16n8k16.row.col.f32.f16.f16.f32 "
        "{%0,%1,%2,%3}, {%4,%5,%6,%7}, {%8,%9}, {%0,%1,%2,%3};"
        : "+f"(c[0]), "+f"(c[1]), "+f"(c[2]), "+f"(c[3])
        : "r"(a0), "r"(a1), "r"(a2), "r"(a3), "r"(b0), "r"(b1));
}

__device__ float g_q[BSZ * SEQ * HD];
__device__ float g_k[BSZ * SEQ * HD];
__device__ float g_v[BSZ * SEQ * HD];
__device__ float g_cos[SEQ * 32];
__device__ float g_sin[SEQ * 32];

// ---------------------------------------------------------------------------
// Kernel 0: RoPE cos/sin table
// ---------------------------------------------------------------------------
__global__ void rope_table_kernel()
{
    const int t = blockIdx.x * blockDim.x + threadIdx.x;
    if (t >= SEQ * 32) return;
    const int pos = t >> 5;
    const int pr  = t & 31;
    const float theta = expf((float)pr * -0.5756462732485114f);
    float sn, cs;
    sincosf((float)pos * theta, &sn, &cs);
    g_cos[t] = cs;
    g_sin[t] = sn;
}

// ---------------------------------------------------------------------------
// Kernel 1: QKV projection via fp16 m16n8k16 mma + RoPE epilogue.
//   grid = (3, 256), 256 thr. Block tile 128x64, warp tile 32x32.
//   Smem rows: 32 data halves + 8 pad = 40 halves = 20 words (banks distinct).
// ---------------------------------------------------------------------------
#define XW 20   // words per smem row

__global__ __launch_bounds__(256) void qkv_rope_kernel(
    const float* __restrict__ x,
    const float* __restrict__ Wq,
    const float* __restrict__ Wk,
    const float* __restrict__ Wv)
{
    const int which = blockIdx.x;
    const float* __restrict__ W = (which == 0) ? Wq : ((which == 1) ? Wk : Wv);
    float* __restrict__ outp    = (which == 0) ? g_q : ((which == 1) ? g_k : g_v);

    const int m0 = blockIdx.y * 128;

    __shared__ uint32 xs[2][128 * XW];
    __shared__ uint32 ws[2][64 * XW];

    const int tid    = threadIdx.x;
    const int lane   = tid & 31;
    const int wid    = tid >> 5;
    const int warp_m = wid & 3;
    const int warp_n = wid >> 2;
    const int lr = lane >> 2;
    const int lc = lane & 3;

    const int xrow = tid >> 3;          // 0..31 (+q*32)
    const int xkq  = tid & 7;           // float4 index within 32-float chunk

    uint2 rx[4], rw[2];

    float c[2][4][4];
    #pragma unroll
    for (int mt = 0; mt < 2; mt++)
        #pragma unroll
        for (int nt = 0; nt < 4; nt++)
            #pragma unroll
            for (int r = 0; r < 4; r++) c[mt][nt][r] = 0.f;

    // prologue: chunk 0 -> regs (converted) -> buf 0
    #pragma unroll
    for (int q = 0; q < 4; q++) {
        float4 t = *(const float4*)&x[(size_t)(m0 + xrow + q * 32) * EMB + xkq * 4];
        rx[q] = make_uint2(ph2(t.x, t.y), ph2(t.z, t.w));
    }
    #pragma unroll
    for (int q = 0; q < 2; q++) {
        float4 t = *(const float4*)&W[(size_t)(xrow + q * 32) * EMB + xkq * 4];
        rw[q] = make_uint2(ph2(t.x, t.y), ph2(t.z, t.w));
    }
    #pragma unroll
    for (int q = 0; q < 4; q++)
        *(uint2*)&xs[0][(xrow + q * 32) * XW + xkq * 2] = rx[q];
    #pragma unroll
    for (int q = 0; q < 2; q++)
        *(uint2*)&ws[0][(xrow + q * 32) * XW + xkq * 2] = rw[q];
    __syncthreads();

    const int NCH = EMB / 32;   // 24
    for (int ec = 0; ec < NCH; ec++) {
        const int cur = ec & 1;
        const bool more = (ec + 1 < NCH);
        if (more) {
            const int e1 = (ec + 1) * 32;
            #pragma unroll
            for (int q = 0; q < 4; q++) {
                float4 t = *(const float4*)&x[(size_t)(m0 + xrow + q * 32) * EMB + e1 + xkq * 4];
                rx[q] = make_uint2(ph2(t.x, t.y), ph2(t.z, t.w));
            }
            #pragma unroll
            for (int q = 0; q < 2; q++) {
                float4 t = *(const float4*)&W[(size_t)(xrow + q * 32) * EMB + e1 + xkq * 4];
                rw[q] = make_uint2(ph2(t.x, t.y), ph2(t.z, t.w));
            }
        }

        #pragma unroll
        for (int ks = 0; ks < 2; ks++) {      // two k16 steps per 32-chunk
            const int kb = ks * 8;            // word offset of k-chunk
            uint32 a[2][4];
            #pragma unroll
            for (int mt = 0; mt < 2; mt++) {
                const int rb = warp_m * 32 + mt * 16 + lr;
                a[mt][0] = xs[cur][rb * XW + kb + lc];
                a[mt][1] = xs[cur][(rb + 8) * XW + kb + lc];
                a[mt][2] = xs[cur][rb * XW + kb + lc + 4];
                a[mt][3] = xs[cur][(rb + 8) * XW + kb + lc + 4];
            }
            uint32 bb[4][2];
            #pragma unroll
            for (int nt = 0; nt < 4; nt++) {
                const int nb = warp_n * 32 + nt * 8 + lr;
                bb[nt][0] = ws[cur][nb * XW + kb + lc];
                bb[nt][1] = ws[cur][nb * XW + kb + lc + 4];
            }
            #pragma unroll
            for (int mt = 0; mt < 2; mt++)
                #pragma unroll
                for (int nt = 0; nt < 4; nt++)
                    mma_f16(c[mt][nt], a[mt][0], a[mt][1], a[mt][2], a[mt][3],
                            bb[nt][0], bb[nt][1]);
        }

        if (more) {
            const int nxt = cur ^ 1;
            #pragma unroll
            for (int q = 0; q < 4; q++)
                *(uint2*)&xs[nxt][(xrow + q * 32) * XW + xkq * 2] = rx[q];
            #pragma unroll
            for (int q = 0; q < 2; q++)
                *(uint2*)&ws[nxt][(xrow + q * 32) * XW + xkq * 2] = rw[q];
            __syncthreads();
        }
    }

    if (which < 2) {
        #pragma unroll
        for (int mt = 0; mt < 2; mt++) {
            const int r0 = m0 + warp_m * 32 + mt * 16 + lr;
            const int r1 = r0 + 8;
            const int p0 = r0 & (SEQ - 1);
            const int p1 = r1 & (SEQ - 1);
            #pragma unroll
            for (int nt = 0; nt < 4; nt++) {
                const int d0   = warp_n * 32 + nt * 8 + 2 * lc;
                const int pair = d0 >> 1;
                {
                    const float cs = g_cos[p0 * 32 + pair];
                    const float sn = g_sin[p0 * 32 + pair];
                    const float av = c[mt][nt][0], bv = c[mt][nt][1];
                    *(ull*)&outp[(size_t)r0 * HD + d0] = pk2(av * cs - bv * sn, bv * cs + av * sn);
                }
                {
                    const float cs = g_cos[p1 * 32 + pair];
                    const float sn = g_sin[p1 * 32 + pair];
                    const float av = c[mt][nt][2], bv = c[mt][nt][3];
                    *(ull*)&outp[(size_t)r1 * HD + d0] = pk2(av * cs - bv * sn, bv * cs + av * sn);
                }
            }
        }
    } else {
        #pragma unroll
        for (int mt = 0; mt < 2; mt++) {
            const int r0 = m0 + warp_m * 32 + mt * 16 + lr;
            #pragma unroll
            for (int nt = 0; nt < 4; nt++) {
                const int d0 = warp_n * 32 + nt * 8 + 2 * lc;
                *(ull*)&outp[(size_t)r0 * HD + d0]       = pk2(c[mt][nt][0], c[mt][nt][1]);
                *(ull*)&outp[(size_t)(r0 + 8) * HD + d0] = pk2(c[mt][nt][2], c[mt][nt][3]);
            }
        }
    }
}

// ---------------------------------------------------------------------------
// Kernel 2: causal flash attention — fp16 m16n8k16, Q fragments in registers,
//   K as [kv][h] fp16, V kv-paired as Vp[h][kvpair], double-buffered K/V.
//   Row stride = 36 words (72 halves): fragment banks 4*lr+lc, distinct.
// ---------------------------------------------------------------------------
#define AW 36

__global__ __launch_bounds__(128) void attn_kernel(float* __restrict__ out)
{
    extern __shared__ uint32 smu[];
    uint32* Ps = smu;                     // [64 q][36w]   P fp16 [q][kv]
    uint32* Ks = Ps + 64 * AW;            // [2][64 kv][36w]  K fp16 [kv][h]
    uint32* Vp = Ks + 2 * 64 * AW;        // [2][64 h][36w]   V paired [h][kvpair]

    const int b  = blockIdx.y;
    const int qt = (SEQ / 64 - 1) - blockIdx.x;   // largest work first
    const int q0 = qt * 64;

    const float* __restrict__ qp = g_q + ((size_t)b * SEQ + q0) * HD;
    const float* __restrict__ kp = g_k + (size_t)b * SEQ * HD;
    const float* __restrict__ vp = g_v + (size_t)b * SEQ * HD;

    const int tid  = threadIdx.x;
    const int lane = tid & 31;
    const int w    = tid >> 5;
    const int lr   = lane >> 2;
    const int lc   = lane & 3;

    // K staging task: p = tid + q*128, q<8: row p>>4 (0..63), quad p&15
    // V staging task: p = tid + q*128, q<4: kvpair p&31, hquad p>>5 (0..15)
    uint2  rk[8];
    uint32 rv[4][4];

    // ---- Q fragments -> registers (loaded once, fp32 global -> fp16) ----
    uint32 qa[4][4];
    {
        const float* q0p = qp + (size_t)(w * 16 + lr) * HD;
        const float* q1p = q0p + 8 * HD;
        #pragma unroll
        for (int ks = 0; ks < 4; ks++) {
            const int k = ks * 16 + 2 * lc;
            float2 t0 = *(const float2*)&q0p[k];
            float2 t1 = *(const float2*)&q1p[k];
            float2 t2 = *(const float2*)&q0p[k + 8];
            float2 t3 = *(const float2*)&q1p[k + 8];
            qa[ks][0] = ph2(t0.x, t0.y);
            qa[ks][1] = ph2(t1.x, t1.y);
            qa[ks][2] = ph2(t2.x, t2.y);
            qa[ks][3] = ph2(t3.x, t3.y);
        }
    }

    // ---- prologue: K/V tile 0 ----
    #pragma unroll
    for (int q = 0; q < 8; q++) {
        const int p = tid + q * 128;
        float4 t = ((const float4*)(kp))[p];
        rk[q] = make_uint2(ph2(t.x, t.y), ph2(t.z, t.w));
    }
    #pragma unroll
    for (int q = 0; q < 4; q++) {
        const int p  = tid + q * 128;
        const int rp = p & 31, hq = p >> 5;
        float4 va = ((const float4*)(vp + (size_t)(2 * rp) * HD))[hq];
        float4 vb = ((const float4*)(vp + (size_t)(2 * rp + 1) * HD))[hq];
        rv[q][0] = ph2(va.x, vb.x); rv[q][1] = ph2(va.y, vb.y);
        rv[q][2] = ph2(va.z, vb.z); rv[q][3] = ph2(va.w, vb.w);
    }
    #pragma unroll
    for (int q = 0; q < 8; q++) {
        const int p = tid + q * 128;
        const int r = p >> 4, hq = p & 15;
        *(uint2*)&Ks[r * AW + hq * 2] = rk[q];
    }
    #pragma unroll
    for (int q = 0; q < 4; q++) {
        const int p  = tid + q * 128;
        const int rp = p & 31, hq = p >> 5;
        #pragma unroll
        for (int i = 0; i < 4; i++)
            Vp[(hq * 4 + i) * AW + rp] = rv[q][i];
    }
    __syncthreads();

    float m_r[2] = {-1e30f, -1e30f};
    float l_r[2] = {0.f, 0.f};
    float o[8][4];
    #pragma unroll
    for (int nt = 0; nt < 8; nt++)
        #pragma unroll
        for (int r = 0; r < 4; r++) o[nt][r] = 0.f;

    const float sc2 = 0.03608439182435161f * 1.4426950408889634f;  // scale*log2e
    const int ntiles = qt + 1;
    const int row0 = q0 + w * 16 + lr;
    const int row1 = row0 + 8;

    for (int t = 0; t < ntiles; t++) {
        const int cur  = t & 1;
        const bool more = (t + 1 < ntiles);
        uint32* Kc = Ks + cur * 64 * AW;
        uint32* Vc = Vp + cur * 64 * AW;

        if (more) {
            const int k1 = (t + 1) * 64;
            #pragma unroll
            for (int q = 0; q < 8; q++) {
                const int p = tid + q * 128;
                float4 tk = ((const float4*)(kp + (size_t)k1 * HD))[p];
                rk[q] = make_uint2(ph2(tk.x, tk.y), ph2(tk.z, tk.w));
            }
            #pragma unroll
            for (int q = 0; q < 4; q++) {
                const int p  = tid + q * 128;
                const int rp = p & 31, hq = p >> 5;
                float4 va = ((const float4*)(vp + (size_t)(k1 + 2 * rp) * HD))[hq];
                float4 vb = ((const float4*)(vp + (size_t)(k1 + 2 * rp + 1) * HD))[hq];
                rv[q][0] = ph2(va.x, vb.x); rv[q][1] = ph2(va.y, vb.y);
                rv[q][2] = ph2(va.z, vb.z); rv[q][3] = ph2(va.w, vb.w);
            }
        }

        // ---- S = Q K^T ----
        float s[8][4];
        #pragma unroll
        for (int nt = 0; nt < 8; nt++)
            #pragma unroll
            for (int r = 0; r < 4; r++) s[nt][r] = 0.f;

        #pragma unroll
        for (int ks = 0; ks < 4; ks++) {
            const int kb = ks * 8;
            #pragma unroll
            for (int nt = 0; nt < 8; nt++) {
                const int nb = nt * 8 + lr;
                const uint32 b0 = Kc[nb * AW + kb + lc];
                const uint32 b1 = Kc[nb * AW + kb + lc + 4];
                mma_f16(s[nt], qa[ks][0], qa[ks][1], qa[ks][2], qa[ks][3], b0, b1);
            }
        }

        // scale (log2 domain) + causal mask
        const bool diag = (t == qt);
        #pragma unroll
        for (int nt = 0; nt < 8; nt++) {
            const int col = t * 64 + nt * 8 + 2 * lc;
            #pragma unroll
            for (int r = 0; r < 4; r++) {
                float sv = s[nt][r] * sc2;
                if (diag) {
                    const int gr = (r < 2) ? row0 : row1;
                    const int gc = col + (r & 1);
                    if (gc > gr) sv = -1e30f;
                }
                s[nt][r] = sv;
            }
        }

        // ---- online softmax ----
        float alpha[2];
        #pragma unroll
        for (int h = 0; h < 2; h++) {
            float rm = -1e30f;
            #pragma unroll
            for (int nt = 0; nt < 8; nt++)
                rm = fmaxf(rm, fmaxf(s[nt][2 * h], s[nt][2 * h + 1]));
            rm = fmaxf(rm, __shfl_xor_sync(0xffffffffu, rm, 1));
            rm = fmaxf(rm, __shfl_xor_sync(0xffffffffu, rm, 2));
            const float mnew = fmaxf(m_r[h], rm);
            alpha[h] = exp2f(m_r[h] - mnew);
            m_r[h] = mnew;

            float rs = 0.f;
            #pragma unroll
            for (int nt = 0; nt < 8; nt++) {
                const float p0 = exp2f(s[nt][2 * h]     - mnew);
                const float p1 = exp2f(s[nt][2 * h + 1] - mnew);
                s[nt][2 * h] = p0; s[nt][2 * h + 1] = p1;
                rs += p0 + p1;
            }
            rs += __shfl_xor_sync(0xffffffffu, rs, 1);
            rs += __shfl_xor_sync(0xffffffffu, rs, 2);
            l_r[h] = l_r[h] * alpha[h] + rs;
        }

        // rescale O; stage P as fp16 (warp-private rows)
        const int prow = w * 16 + lr;
        #pragma unroll
        for (int nt = 0; nt < 8; nt++) {
            o[nt][0] *= alpha[0]; o[nt][1] *= alpha[0];
            o[nt][2] *= alpha[1]; o[nt][3] *= alpha[1];
            Ps[prow * AW + nt * 4 + lc]       = ph2(s[nt][0], s[nt][1]);
            Ps[(prow + 8) * AW + nt * 4 + lc] = ph2(s[nt][2], s[nt][3]);
        }
        __syncwarp();

        // ---- O += P V ----
        #pragma unroll
        for (int ks = 0; ks < 4; ks++) {
            const int kb = ks * 8;
            const uint32 a0 = Ps[prow * AW + kb + lc];
            const uint32 a1 = Ps[(prow + 8) * AW + kb + lc];
            const uint32 a2 = Ps[prow * AW + kb + lc + 4];
            const uint32 a3 = Ps[(prow + 8) * AW + kb + lc + 4];
            #pragma unroll
            for (int nt = 0; nt < 8; nt++) {
                const int nb = nt * 8 + lr;
                const uint32 b0 = Vc[nb * AW + kb + lc];
                const uint32 b1 = Vc[nb * AW + kb + lc + 4];
                mma_f16(o[nt], a0, a1, a2, a3, b0, b1);
            }
        }

        if (more) {
            const int nxt = cur ^ 1;
            uint32* Kn = Ks + nxt * 64 * AW;
            uint32* Vn = Vp + nxt * 64 * AW;
            #pragma unroll
            for (int q = 0; q < 8; q++) {
                const int p = tid + q * 128;
                const int r = p >> 4, hq = p & 15;
                *(uint2*)&Kn[r * AW + hq * 2] = rk[q];
            }
            #pragma unroll
            for (int q = 0; q < 4; q++) {
                const int p  = tid + q * 128;
                const int rp = p & 31, hq = p >> 5;
                #pragma unroll
                for (int i = 0; i < 4; i++)
                    Vn[(hq * 4 + i) * AW + rp] = rv[q][i];
            }
            __syncthreads();
        }
    }

    const float il0 = 1.0f / l_r[0];
    const float il1 = 1.0f / l_r[1];
    #pragma unroll
    for (int nt = 0; nt < 8; nt++) {
        const int d0 = nt * 8 + 2 * lc;
        *(ull*)&out[((size_t)b * SEQ + row0) * HD + d0] = pk2(o[nt][0] * il0, o[nt][1] * il0);
        *(ull*)&out[((size_t)b * SEQ + row1) * HD + d0] = pk2(o[nt][2] * il1, o[nt][3] * il1);
    }
}

extern "C" void kernel_launch(void* const* d_in, const int* in_sizes, int n_in,
                              void* d_out, int out_size)
{
    const float* x  = (const float*)d_in[0];
    const float* Wq = (const float*)d_in[1];
    const float* Wk = (const float*)d_in[2];
    const float* Wv = (const float*)d_in[3];
    float* out = (float*)d_out;

    rope_table_kernel<<<(SEQ * 32 + 255) / 256, 256>>>();

    dim3 g1(3, (BSZ * SEQ) / 128);
    qkv_rope_kernel<<<g1, 256>>>(x, Wq, Wk, Wv);

    const int smem = (64 * AW + 2 * 64 * AW + 2 * 64 * AW) * (int)sizeof(uint32); // 46080 B
    cudaFuncSetAttribute(attn_kernel, cudaFuncAttributeMaxDynamicSharedMemorySize, smem);
    dim3 g2(SEQ / 64, BSZ);
    attn_kernel<<<g2, 128, smem>>>(out);
}